// round 1
// baseline (speedup 1.0000x reference)
#include <cuda_runtime.h>
#include <math.h>

#define B_ 8
#define S_ 2048
#define D_ 768
#define DK_ 768
#define MTOT (B_ * S_)   // 16384
#define EPS_ 1e-5f

// ---------------- scratch (device globals; no allocations allowed) ----------
__device__ float g_Q[(size_t)MTOT * DK_];
__device__ float g_K[(size_t)MTOT * DK_];
__device__ float g_V[(size_t)MTOT * DK_];
__device__ float g_Sc[(size_t)B_ * S_ * S_];     // scores / attn probs (134 MB)
__device__ float g_ctx[(size_t)MTOT * DK_];
__device__ float g_ao[(size_t)MTOT * D_];
__device__ float g_pooled[B_ * D_];

// ---------------- reductions -------------------------------------------------
__device__ __forceinline__ float warp_sum(float v) {
    #pragma unroll
    for (int o = 16; o > 0; o >>= 1) v += __shfl_xor_sync(0xFFFFFFFFu, v, o);
    return v;
}
__device__ __forceinline__ float warp_max(float v) {
    #pragma unroll
    for (int o = 16; o > 0; o >>= 1) v = fmaxf(v, __shfl_xor_sync(0xFFFFFFFFu, v, o));
    return v;
}
__device__ __forceinline__ float block_sum(float v, float* sh) {
    __syncthreads();
    int lane = threadIdx.x & 31, w = threadIdx.x >> 5;
    v = warp_sum(v);
    if (lane == 0) sh[w] = v;
    __syncthreads();
    float r = (threadIdx.x < (blockDim.x >> 5)) ? sh[threadIdx.x] : 0.0f;
    if (w == 0) {
        r = warp_sum(r);
        if (lane == 0) sh[0] = r;
    }
    __syncthreads();
    return sh[0];
}
__device__ __forceinline__ float block_max(float v, float* sh) {
    __syncthreads();
    int lane = threadIdx.x & 31, w = threadIdx.x >> 5;
    v = warp_max(v);
    if (lane == 0) sh[w] = v;
    __syncthreads();
    float r = (threadIdx.x < (blockDim.x >> 5)) ? sh[threadIdx.x] : -INFINITY;
    if (w == 0) {
        r = warp_max(r);
        if (lane == 0) sh[0] = r;
    }
    __syncthreads();
    return sh[0];
}

// ---------------- SGEMM: C[M,N] = alpha * A[M,K] @ (TB ? B[N,K]^T : B[K,N]) + bias
// 128x128 tile, BK=8, 256 threads, 8x8 per thread. All dims multiples of 128/8.
template <bool TB>
__global__ void __launch_bounds__(256) sgemm_kernel(
    const float* __restrict__ A, const float* __restrict__ Bm,
    float* __restrict__ C, const float* __restrict__ bias,
    int M, int N, int K, float alpha,
    size_t sA, size_t sB, size_t sC)
{
    __shared__ float As[8][128];
    __shared__ float Bs[8][128];

    A  += blockIdx.z * sA;
    Bm += blockIdx.z * sB;
    C  += blockIdx.z * sC;

    const int tid = threadIdx.x;
    const int m0 = blockIdx.y * 128;
    const int n0 = blockIdx.x * 128;

    const int arow = tid >> 1;            // 0..127
    const int acol = (tid & 1) * 4;       // 0 or 4
    const int brow = tid >> 5;            // 0..7
    const int bcol = (tid & 31) * 4;      // 0..124

    const int ty = tid >> 4;              // 0..15
    const int tx = tid & 15;              // 0..15

    float acc[8][8];
    #pragma unroll
    for (int i = 0; i < 8; i++)
        #pragma unroll
        for (int j = 0; j < 8; j++) acc[i][j] = 0.0f;

    for (int k0 = 0; k0 < K; k0 += 8) {
        float4 av = *(const float4*)(A + (size_t)(m0 + arow) * K + k0 + acol);
        As[acol + 0][arow] = av.x;
        As[acol + 1][arow] = av.y;
        As[acol + 2][arow] = av.z;
        As[acol + 3][arow] = av.w;
        if (TB) {
            float4 bv = *(const float4*)(Bm + (size_t)(n0 + arow) * K + k0 + acol);
            Bs[acol + 0][arow] = bv.x;
            Bs[acol + 1][arow] = bv.y;
            Bs[acol + 2][arow] = bv.z;
            Bs[acol + 3][arow] = bv.w;
        } else {
            float4 bv = *(const float4*)(Bm + (size_t)(k0 + brow) * N + n0 + bcol);
            *(float4*)&Bs[brow][bcol] = bv;
        }
        __syncthreads();

        #pragma unroll
        for (int kk = 0; kk < 8; kk++) {
            float a[8], b[8];
            *(float4*)(a)     = *(const float4*)&As[kk][ty * 8];
            *(float4*)(a + 4) = *(const float4*)&As[kk][ty * 8 + 4];
            *(float4*)(b)     = *(const float4*)&Bs[kk][tx * 8];
            *(float4*)(b + 4) = *(const float4*)&Bs[kk][tx * 8 + 4];
            #pragma unroll
            for (int i = 0; i < 8; i++)
                #pragma unroll
                for (int j = 0; j < 8; j++)
                    acc[i][j] = fmaf(a[i], b[j], acc[i][j]);
        }
        __syncthreads();
    }

    #pragma unroll
    for (int i = 0; i < 8; i++) {
        const int row = m0 + ty * 8 + i;
        #pragma unroll
        for (int j = 0; j < 8; j += 4) {
            const int col = n0 + tx * 8 + j;
            float4 v;
            v.x = acc[i][j + 0] * alpha;
            v.y = acc[i][j + 1] * alpha;
            v.z = acc[i][j + 2] * alpha;
            v.w = acc[i][j + 3] * alpha;
            if (bias) {
                v.x += bias[col + 0]; v.y += bias[col + 1];
                v.z += bias[col + 2]; v.w += bias[col + 3];
            }
            *(float4*)(C + (size_t)row * N + col) = v;
        }
    }
}

// ---------------- row softmax over S_=2048 cols ------------------------------
__global__ void __launch_bounds__(256) softmax_kernel(float* __restrict__ Sc) {
    __shared__ float sh[32];
    const size_t row = blockIdx.x;
    float* p = Sc + row * (size_t)S_;
    const int tid = threadIdx.x;

    float v[8];
    float mx = -INFINITY;
    #pragma unroll
    for (int i = 0; i < 8; i++) {
        v[i] = p[tid + i * 256];
        mx = fmaxf(mx, v[i]);
    }
    mx = block_max(mx, sh);

    float s = 0.0f;
    #pragma unroll
    for (int i = 0; i < 8; i++) {
        v[i] = __expf(v[i] - mx);
        s += v[i];
    }
    s = block_sum(s, sh);
    const float inv = 1.0f / s;
    #pragma unroll
    for (int i = 0; i < 8; i++) p[tid + i * 256] = v[i] * inv;
}

// ---------------- residual + LN + LN, fused, one block per row (768) ---------
__global__ void __launch_bounds__(256) resid_ln2_kernel(
    const float* __restrict__ src, const float* __restrict__ ao,
    const float* __restrict__ w1, const float* __restrict__ b1,
    const float* __restrict__ w2, const float* __restrict__ b2,
    float* __restrict__ xout)
{
    __shared__ float sh[32];
    const size_t row = blockIdx.x;
    const int tid = threadIdx.x;
    const size_t base = row * (size_t)D_;

    float v[3];
    int d[3];
    #pragma unroll
    for (int i = 0; i < 3; i++) {
        d[i] = tid + i * 256;
        v[i] = src[base + d[i]] + ao[base + d[i]];
    }

    // LN1
    float s = v[0] + v[1] + v[2];
    s = block_sum(s, sh);
    const float mu1 = s * (1.0f / (float)D_);
    float sq = 0.0f;
    #pragma unroll
    for (int i = 0; i < 3; i++) { float t = v[i] - mu1; sq += t * t; }
    sq = block_sum(sq, sh);
    const float r1 = rsqrtf(sq * (1.0f / (float)D_) + EPS_);
    #pragma unroll
    for (int i = 0; i < 3; i++)
        v[i] = (v[i] - mu1) * r1 * w1[d[i]] + b1[d[i]];

    // LN2
    s = v[0] + v[1] + v[2];
    s = block_sum(s, sh);
    const float mu2 = s * (1.0f / (float)D_);
    sq = 0.0f;
    #pragma unroll
    for (int i = 0; i < 3; i++) { float t = v[i] - mu2; sq += t * t; }
    sq = block_sum(sq, sh);
    const float r2 = rsqrtf(sq * (1.0f / (float)D_) + EPS_);
    #pragma unroll
    for (int i = 0; i < 3; i++)
        xout[base + d[i]] = (v[i] - mu2) * r2 * w2[d[i]] + b2[d[i]];
}

// ---------------- pooled mean over S ----------------------------------------
__global__ void __launch_bounds__(256) pool_kernel(const float* __restrict__ x,
                                                   float* __restrict__ pooled) {
    const int b = blockIdx.y;
    const int dd = blockIdx.x * 256 + threadIdx.x;   // grid.x = 3
    const float* p = x + (size_t)b * S_ * D_ + dd;
    float s = 0.0f;
    for (int t = 0; t < S_; t++) s += p[(size_t)t * D_];
    pooled[b * D_ + dd] = s * (1.0f / (float)S_);
}

// ---------------- logits: pooled[8,768] @ Wc[768,10] + bc --------------------
__global__ void __launch_bounds__(128) logits_kernel(
    const float* __restrict__ pooled, const float* __restrict__ Wc,
    const float* __restrict__ bc, float* __restrict__ out)
{
    __shared__ float sh[32];
    const int idx = blockIdx.x;       // 0..79
    const int b = idx / 10, o = idx % 10;
    float s = 0.0f;
    for (int dd = threadIdx.x; dd < D_; dd += 128)
        s += pooled[b * D_ + dd] * Wc[dd * 10 + o];
    s = block_sum(s, sh);
    if (threadIdx.x == 0) out[b * 10 + o] = s + bc[o];
}

// ---------------- launch -----------------------------------------------------
extern "C" void kernel_launch(void* const* d_in, const int* in_sizes, int n_in,
                              void* d_out, int out_size) {
    const float* src  = (const float*)d_in[0];
    const float* Wq   = (const float*)d_in[1];
    const float* Wk   = (const float*)d_in[2];
    const float* Wv   = (const float*)d_in[3];
    const float* Wo   = (const float*)d_in[4];
    const float* bo   = (const float*)d_in[5];
    const float* ln1w = (const float*)d_in[6];
    const float* ln1b = (const float*)d_in[7];
    const float* ln2w = (const float*)d_in[8];
    const float* ln2b = (const float*)d_in[9];
    const float* Wc   = (const float*)d_in[10];
    const float* bc   = (const float*)d_in[11];

    float* out    = (float*)d_out;
    float* logits = out;          // [8,10]
    float* xout   = out + B_ * 10; // [8,2048,768]

    float *Q, *K, *V, *Sc, *ctx, *ao, *pooled;
    cudaGetSymbolAddress((void**)&Q,      g_Q);
    cudaGetSymbolAddress((void**)&K,      g_K);
    cudaGetSymbolAddress((void**)&V,      g_V);
    cudaGetSymbolAddress((void**)&Sc,     g_Sc);
    cudaGetSymbolAddress((void**)&ctx,    g_ctx);
    cudaGetSymbolAddress((void**)&ao,     g_ao);
    cudaGetSymbolAddress((void**)&pooled, g_pooled);

    // 1) Q,K,V = src @ W*   [16384,768] x [768,768]
    {
        dim3 grid(DK_ / 128, MTOT / 128, 1);
        sgemm_kernel<false><<<grid, 256>>>(src, Wq, Q, nullptr, MTOT, DK_, D_, 1.0f, 0, 0, 0);
        sgemm_kernel<false><<<grid, 256>>>(src, Wk, K, nullptr, MTOT, DK_, D_, 1.0f, 0, 0, 0);
        sgemm_kernel<false><<<grid, 256>>>(src, Wv, V, nullptr, MTOT, DK_, D_, 1.0f, 0, 0, 0);
    }
    // 2) scores = Q @ K^T * 1/sqrt(DK), per batch
    {
        dim3 grid(S_ / 128, S_ / 128, B_);
        const float alpha = rsqrtf((float)DK_);
        sgemm_kernel<true><<<grid, 256>>>(Q, K, Sc, nullptr, S_, S_, DK_, alpha,
                                          (size_t)S_ * DK_, (size_t)S_ * DK_,
                                          (size_t)S_ * S_);
    }
    // 3) softmax rows
    softmax_kernel<<<B_ * S_, 256>>>(Sc);
    // 4) ctx = attn @ V, per batch  [2048,2048] x [2048,768]
    {
        dim3 grid(DK_ / 128, S_ / 128, B_);
        sgemm_kernel<false><<<grid, 256>>>(Sc, V, ctx, nullptr, S_, DK_, S_, 1.0f,
                                           (size_t)S_ * S_, (size_t)S_ * DK_,
                                           (size_t)S_ * DK_);
    }
    // 5) ao = ctx @ Wo + bo
    {
        dim3 grid(D_ / 128, MTOT / 128, 1);
        sgemm_kernel<false><<<grid, 256>>>(ctx, Wo, ao, bo, MTOT, D_, DK_, 1.0f, 0, 0, 0);
    }
    // 6) x = LN2(LN1(src + ao))
    resid_ln2_kernel<<<MTOT, 256>>>(src, ao, ln1w, ln1b, ln2w, ln2b, xout);
    // 7) pooled mean over S
    {
        dim3 grid(D_ / 256, B_);
        pool_kernel<<<grid, 256>>>(xout, pooled);
    }
    // 8) logits
    logits_kernel<<<B_ * 10, 128>>>(pooled, Wc, bc, logits);
}

// round 2
// speedup vs baseline: 1.3186x; 1.3186x over previous
#include <cuda_runtime.h>
#include <mma.h>
#include <math.h>

using namespace nvcuda;

#define B_ 8
#define S_ 2048
#define D_ 768
#define DK_ 768
#define MTOT (B_ * S_)   // 16384
#define EPS_ 1e-5f

#define BKP 20            // padded lds for [row][k] tiles (16+4)
#define BNP 132           // padded lds for [k][n] tiles (128+4)

// ---------------- scratch (device globals; no allocations allowed) ----------
__device__ float g_Q[(size_t)MTOT * DK_];
__device__ float g_K[(size_t)MTOT * DK_];
__device__ float g_V[(size_t)MTOT * DK_];
__device__ float g_Sc[(size_t)B_ * S_ * S_];     // scores / attn probs (134 MB)
__device__ float g_ctx[(size_t)MTOT * DK_];
__device__ float g_ao[(size_t)MTOT * D_];
__device__ float g_pooled[B_ * D_];

// ---------------- reductions -------------------------------------------------
__device__ __forceinline__ float warp_sum(float v) {
    #pragma unroll
    for (int o = 16; o > 0; o >>= 1) v += __shfl_xor_sync(0xFFFFFFFFu, v, o);
    return v;
}
__device__ __forceinline__ float warp_max(float v) {
    #pragma unroll
    for (int o = 16; o > 0; o >>= 1) v = fmaxf(v, __shfl_xor_sync(0xFFFFFFFFu, v, o));
    return v;
}
__device__ __forceinline__ float block_sum(float v, float* sh) {
    __syncthreads();
    int lane = threadIdx.x & 31, w = threadIdx.x >> 5;
    v = warp_sum(v);
    if (lane == 0) sh[w] = v;
    __syncthreads();
    float r = (threadIdx.x < (blockDim.x >> 5)) ? sh[threadIdx.x] : 0.0f;
    if (w == 0) {
        r = warp_sum(r);
        if (lane == 0) sh[0] = r;
    }
    __syncthreads();
    return sh[0];
}
__device__ __forceinline__ float block_max(float v, float* sh) {
    __syncthreads();
    int lane = threadIdx.x & 31, w = threadIdx.x >> 5;
    v = warp_max(v);
    if (lane == 0) sh[w] = v;
    __syncthreads();
    float r = (threadIdx.x < (blockDim.x >> 5)) ? sh[threadIdx.x] : -INFINITY;
    if (w == 0) {
        r = warp_max(r);
        if (lane == 0) sh[0] = r;
    }
    __syncthreads();
    return sh[0];
}

// ---------------- TF32 tensor-core GEMM --------------------------------------
// C[M,N] = alpha * A[M,K] @ (TB ? B[N,K]^T : B[K,N])
// 128x128 block tile, BK=16, 256 threads (8 warps: 4 along M x 2 along N),
// warp tile 32x64 = 2x4 wmma m16n16k8 tiles. cp.async double buffering.
template <bool TB>
__global__ void __launch_bounds__(256) gemm_tf32(
    const float* __restrict__ A, const float* __restrict__ Bm,
    float* __restrict__ C,
    int M, int N, int K, float alpha,
    size_t sA, size_t sB, size_t sC)
{
    __shared__ float As[2][128 * BKP];
    __shared__ float Bs[2][128 * BKP];   // covers both layouts (16*BNP=2112 < 2560)

    A  += blockIdx.z * sA;
    Bm += blockIdx.z * sB;
    C  += blockIdx.z * sC;

    const int tid = threadIdx.x;
    const int wid = tid >> 5;
    const int wm  = wid & 3;      // 0..3  (M direction, 32 rows each)
    const int wn  = wid >> 2;     // 0..1  (N direction, 64 cols each)
    const int m0  = blockIdx.y * 128;
    const int n0  = blockIdx.x * 128;

    wmma::fragment<wmma::accumulator, 16, 16, 8, float> acc[2][4];
    #pragma unroll
    for (int i = 0; i < 2; i++)
        #pragma unroll
        for (int j = 0; j < 4; j++) wmma::fill_fragment(acc[i][j], 0.0f);

    auto load_stage = [&](int buf, int k0) {
        // A tile: 128 rows x 16 cols, float4 per thread x2
        #pragma unroll
        for (int i = 0; i < 2; i++) {
            int idx = tid + i * 256;
            int r = idx >> 2, c = (idx & 3) * 4;
            const float* gp = A + (size_t)(m0 + r) * K + k0 + c;
            unsigned sp = (unsigned)__cvta_generic_to_shared(&As[buf][r * BKP + c]);
            asm volatile("cp.async.cg.shared.global [%0], [%1], 16;\n" :: "r"(sp), "l"(gp));
        }
        if (TB) {
            // B tile stored [n][k]: 128 rows x 16 cols
            #pragma unroll
            for (int i = 0; i < 2; i++) {
                int idx = tid + i * 256;
                int r = idx >> 2, c = (idx & 3) * 4;
                const float* gp = Bm + (size_t)(n0 + r) * K + k0 + c;
                unsigned sp = (unsigned)__cvta_generic_to_shared(&Bs[buf][r * BKP + c]);
                asm volatile("cp.async.cg.shared.global [%0], [%1], 16;\n" :: "r"(sp), "l"(gp));
            }
        } else {
            // B tile stored [k][n]: 16 rows x 128 cols
            #pragma unroll
            for (int i = 0; i < 2; i++) {
                int idx = tid + i * 256;
                int r = idx >> 5, c = (idx & 31) * 4;
                const float* gp = Bm + (size_t)(k0 + r) * N + n0 + c;
                unsigned sp = (unsigned)__cvta_generic_to_shared(&Bs[buf][r * BNP + c]);
                asm volatile("cp.async.cg.shared.global [%0], [%1], 16;\n" :: "r"(sp), "l"(gp));
            }
        }
        asm volatile("cp.async.commit_group;\n" ::);
    };

    auto compute = [&](int buf) {
        #pragma unroll
        for (int kk = 0; kk < 16; kk += 8) {
            wmma::fragment<wmma::matrix_a, 16, 16, 8, wmma::precision::tf32, wmma::row_major> af[2];
            #pragma unroll
            for (int i = 0; i < 2; i++) {
                wmma::load_matrix_sync(af[i], &As[buf][(wm * 32 + i * 16) * BKP + kk], BKP);
                #pragma unroll
                for (int t = 0; t < af[i].num_elements; t++)
                    af[i].x[t] = wmma::__float_to_tf32(af[i].x[t]);
            }
            if (TB) {
                wmma::fragment<wmma::matrix_b, 16, 16, 8, wmma::precision::tf32, wmma::col_major> bf[4];
                #pragma unroll
                for (int j = 0; j < 4; j++) {
                    wmma::load_matrix_sync(bf[j], &Bs[buf][(wn * 64 + j * 16) * BKP + kk], BKP);
                    #pragma unroll
                    for (int t = 0; t < bf[j].num_elements; t++)
                        bf[j].x[t] = wmma::__float_to_tf32(bf[j].x[t]);
                }
                #pragma unroll
                for (int i = 0; i < 2; i++)
                    #pragma unroll
                    for (int j = 0; j < 4; j++)
                        wmma::mma_sync(acc[i][j], af[i], bf[j], acc[i][j]);
            } else {
                wmma::fragment<wmma::matrix_b, 16, 16, 8, wmma::precision::tf32, wmma::row_major> bf[4];
                #pragma unroll
                for (int j = 0; j < 4; j++) {
                    wmma::load_matrix_sync(bf[j], &Bs[buf][kk * BNP + wn * 64 + j * 16], BNP);
                    #pragma unroll
                    for (int t = 0; t < bf[j].num_elements; t++)
                        bf[j].x[t] = wmma::__float_to_tf32(bf[j].x[t]);
                }
                #pragma unroll
                for (int i = 0; i < 2; i++)
                    #pragma unroll
                    for (int j = 0; j < 4; j++)
                        wmma::mma_sync(acc[i][j], af[i], bf[j], acc[i][j]);
            }
        }
    };

    const int nk = K / 16;
    load_stage(0, 0);
    for (int s = 0; s < nk; s++) {
        asm volatile("cp.async.wait_group 0;\n" ::);
        __syncthreads();
        if (s + 1 < nk) load_stage((s + 1) & 1, (s + 1) * 16);
        compute(s & 1);
        __syncthreads();
    }

    #pragma unroll
    for (int i = 0; i < 2; i++) {
        #pragma unroll
        for (int j = 0; j < 4; j++) {
            #pragma unroll
            for (int t = 0; t < acc[i][j].num_elements; t++)
                acc[i][j].x[t] *= alpha;
            wmma::store_matrix_sync(
                C + (size_t)(m0 + wm * 32 + i * 16) * N + n0 + wn * 64 + j * 16,
                acc[i][j], N, wmma::mem_row_major);
        }
    }
}

// ---------------- row softmax over S_=2048 cols ------------------------------
__global__ void __launch_bounds__(256) softmax_kernel(float* __restrict__ Sc) {
    __shared__ float sh[32];
    const size_t row = blockIdx.x;
    float* p = Sc + row * (size_t)S_;
    const int tid = threadIdx.x;

    float v[8];
    float mx = -INFINITY;
    #pragma unroll
    for (int i = 0; i < 8; i++) {
        v[i] = p[tid + i * 256];
        mx = fmaxf(mx, v[i]);
    }
    mx = block_max(mx, sh);

    float s = 0.0f;
    #pragma unroll
    for (int i = 0; i < 8; i++) {
        v[i] = __expf(v[i] - mx);
        s += v[i];
    }
    s = block_sum(s, sh);
    const float inv = 1.0f / s;
    #pragma unroll
    for (int i = 0; i < 8; i++) p[tid + i * 256] = v[i] * inv;
}

// ---------------- residual(+bo) + LN + LN, fused -----------------------------
__global__ void __launch_bounds__(256) resid_ln2_kernel(
    const float* __restrict__ src, const float* __restrict__ ao,
    const float* __restrict__ bo,
    const float* __restrict__ w1, const float* __restrict__ b1,
    const float* __restrict__ w2, const float* __restrict__ b2,
    float* __restrict__ xout)
{
    __shared__ float sh[32];
    const size_t row = blockIdx.x;
    const int tid = threadIdx.x;
    const size_t base = row * (size_t)D_;

    float v[3];
    int d[3];
    #pragma unroll
    for (int i = 0; i < 3; i++) {
        d[i] = tid + i * 256;
        v[i] = src[base + d[i]] + ao[base + d[i]] + bo[d[i]];
    }

    float s = v[0] + v[1] + v[2];
    s = block_sum(s, sh);
    const float mu1 = s * (1.0f / (float)D_);
    float sq = 0.0f;
    #pragma unroll
    for (int i = 0; i < 3; i++) { float t = v[i] - mu1; sq += t * t; }
    sq = block_sum(sq, sh);
    const float r1 = rsqrtf(sq * (1.0f / (float)D_) + EPS_);
    #pragma unroll
    for (int i = 0; i < 3; i++)
        v[i] = (v[i] - mu1) * r1 * w1[d[i]] + b1[d[i]];

    s = v[0] + v[1] + v[2];
    s = block_sum(s, sh);
    const float mu2 = s * (1.0f / (float)D_);
    sq = 0.0f;
    #pragma unroll
    for (int i = 0; i < 3; i++) { float t = v[i] - mu2; sq += t * t; }
    sq = block_sum(sq, sh);
    const float r2 = rsqrtf(sq * (1.0f / (float)D_) + EPS_);
    #pragma unroll
    for (int i = 0; i < 3; i++)
        xout[base + d[i]] = (v[i] - mu2) * r2 * w2[d[i]] + b2[d[i]];
}

// ---------------- pooled mean over S ----------------------------------------
__global__ void __launch_bounds__(256) pool_kernel(const float* __restrict__ x,
                                                   float* __restrict__ pooled) {
    const int b = blockIdx.y;
    const int dd = blockIdx.x * 256 + threadIdx.x;
    const float* p = x + (size_t)b * S_ * D_ + dd;
    float s = 0.0f;
    for (int t = 0; t < S_; t++) s += p[(size_t)t * D_];
    pooled[b * D_ + dd] = s * (1.0f / (float)S_);
}

// ---------------- logits -----------------------------------------------------
__global__ void __launch_bounds__(128) logits_kernel(
    const float* __restrict__ pooled, const float* __restrict__ Wc,
    const float* __restrict__ bc, float* __restrict__ out)
{
    __shared__ float sh[32];
    const int idx = blockIdx.x;
    const int b = idx / 10, o = idx % 10;
    float s = 0.0f;
    for (int dd = threadIdx.x; dd < D_; dd += 128)
        s += pooled[b * D_ + dd] * Wc[dd * 10 + o];
    s = block_sum(s, sh);
    if (threadIdx.x == 0) out[b * 10 + o] = s + bc[o];
}

// ---------------- launch -----------------------------------------------------
extern "C" void kernel_launch(void* const* d_in, const int* in_sizes, int n_in,
                              void* d_out, int out_size) {
    const float* src  = (const float*)d_in[0];
    const float* Wq   = (const float*)d_in[1];
    const float* Wk   = (const float*)d_in[2];
    const float* Wv   = (const float*)d_in[3];
    const float* Wo   = (const float*)d_in[4];
    const float* bo   = (const float*)d_in[5];
    const float* ln1w = (const float*)d_in[6];
    const float* ln1b = (const float*)d_in[7];
    const float* ln2w = (const float*)d_in[8];
    const float* ln2b = (const float*)d_in[9];
    const float* Wc   = (const float*)d_in[10];
    const float* bc   = (const float*)d_in[11];

    float* out    = (float*)d_out;
    float* logits = out;           // [8,10]
    float* xout   = out + B_ * 10; // [8,2048,768]

    float *Q, *K, *V, *Sc, *ctx, *ao, *pooled;
    cudaGetSymbolAddress((void**)&Q,      g_Q);
    cudaGetSymbolAddress((void**)&K,      g_K);
    cudaGetSymbolAddress((void**)&V,      g_V);
    cudaGetSymbolAddress((void**)&Sc,     g_Sc);
    cudaGetSymbolAddress((void**)&ctx,    g_ctx);
    cudaGetSymbolAddress((void**)&ao,     g_ao);
    cudaGetSymbolAddress((void**)&pooled, g_pooled);

    // 1) Q,K,V = src @ W*   [16384,768] x [768,768]
    {
        dim3 grid(DK_ / 128, MTOT / 128, 1);
        gemm_tf32<false><<<grid, 256>>>(src, Wq, Q, MTOT, DK_, D_, 1.0f, 0, 0, 0);
        gemm_tf32<false><<<grid, 256>>>(src, Wk, K, MTOT, DK_, D_, 1.0f, 0, 0, 0);
        gemm_tf32<false><<<grid, 256>>>(src, Wv, V, MTOT, DK_, D_, 1.0f, 0, 0, 0);
    }
    // 2) scores = Q @ K^T * 1/sqrt(DK), per batch
    {
        dim3 grid(S_ / 128, S_ / 128, B_);
        const float alpha = rsqrtf((float)DK_);
        gemm_tf32<true><<<grid, 256>>>(Q, K, Sc, S_, S_, DK_, alpha,
                                       (size_t)S_ * DK_, (size_t)S_ * DK_,
                                       (size_t)S_ * S_);
    }
    // 3) softmax rows
    softmax_kernel<<<B_ * S_, 256>>>(Sc);
    // 4) ctx = attn @ V, per batch  [2048,2048] x [2048,768]
    {
        dim3 grid(DK_ / 128, S_ / 128, B_);
        gemm_tf32<false><<<grid, 256>>>(Sc, V, ctx, S_, DK_, S_, 1.0f,
                                        (size_t)S_ * S_, (size_t)S_ * DK_,
                                        (size_t)S_ * DK_);
    }
    // 5) ao = ctx @ Wo   (bo folded into resid kernel)
    {
        dim3 grid(D_ / 128, MTOT / 128, 1);
        gemm_tf32<false><<<grid, 256>>>(ctx, Wo, ao, MTOT, D_, DK_, 1.0f, 0, 0, 0);
    }
    // 6) x = LN2(LN1(src + ao + bo))
    resid_ln2_kernel<<<MTOT, 256>>>(src, ao, bo, ln1w, ln1b, ln2w, ln2b, xout);
    // 7) pooled mean over S
    {
        dim3 grid(D_ / 256, B_);
        pool_kernel<<<grid, 256>>>(xout, pooled);
    }
    // 8) logits
    logits_kernel<<<B_ * 10, 128>>>(pooled, Wc, bc, logits);
}

// round 4
// speedup vs baseline: 3.1447x; 2.3848x over previous
#include <cuda_runtime.h>
#include <cstdint>
#include <math.h>

#define B_ 8
#define S_ 2048
#define D_ 768
#define DK_ 768
#define MTOT (B_ * S_)   // 16384
#define EPS_ 1e-5f

// ---------------- scratch (device globals; no allocations allowed) ----------
__device__ float g_Q[(size_t)MTOT * DK_];
__device__ float g_K[(size_t)MTOT * DK_];
__device__ float g_V[(size_t)MTOT * DK_];
__device__ float g_Vt[(size_t)B_ * DK_ * S_];    // V transposed per batch [DK,S]
__device__ float g_Sc[(size_t)B_ * S_ * S_];     // scores / attn probs (134 MB)
__device__ float g_ctx[(size_t)MTOT * DK_];
__device__ float g_ao[(size_t)MTOT * D_];
__device__ float g_pooled[B_ * D_];
__device__ float g_WqT[D_ * DK_];
__device__ float g_WkT[D_ * DK_];
__device__ float g_WvT[D_ * DK_];
__device__ float g_WoT[DK_ * D_];

// ---------------- helpers ----------------------------------------------------
__device__ __forceinline__ void cp_async16(void* sp, const void* gp) {
    unsigned s = (unsigned)__cvta_generic_to_shared(sp);
    asm volatile("cp.async.cg.shared.global [%0], [%1], 16;\n" :: "r"(s), "l"(gp));
}
__device__ __forceinline__ uint32_t f2tf32(float f) {
    uint32_t r;
    asm("cvt.rna.tf32.f32 %0, %1;" : "=r"(r) : "f"(f));
    return r;
}
__device__ __forceinline__ void mma_tf32(float* d, const uint32_t* a, const uint32_t* b) {
    asm volatile(
        "mma.sync.aligned.m16n8k8.row.col.f32.tf32.tf32.f32 "
        "{%0,%1,%2,%3}, {%4,%5,%6,%7}, {%8,%9}, {%0,%1,%2,%3};"
        : "+f"(d[0]), "+f"(d[1]), "+f"(d[2]), "+f"(d[3])
        : "r"(a[0]), "r"(a[1]), "r"(a[2]), "r"(a[3]), "r"(b[0]), "r"(b[1]));
}

// ---------------- TF32 mma.sync GEMM: C[M,N] = alpha * A[M,K] @ Bt[N,K]^T ----
// 128x128 CTA tile, BK=32, double-buffered cp.async, 8 warps (4Mx2N), warp 32x64.
#define RS 36                        // smem row stride in floats (conflict-free)
#define TILE_F (128 * RS)            // floats per matrix tile
#define STAGE_F (2 * TILE_F)         // A + B
#define GEMM_SMEM (2 * STAGE_F * 4)  // bytes (73728)

__global__ void __launch_bounds__(256, 2) gemm_mma(
    const float* __restrict__ A, const float* __restrict__ Bt,
    float* __restrict__ C, int M, int N, int K, float alpha,
    size_t sA, size_t sB, size_t sC)
{
    extern __shared__ float smem[];

    A  += blockIdx.z * sA;
    Bt += blockIdx.z * sB;
    C  += blockIdx.z * sC;

    const int tid = threadIdx.x;
    const int wid = tid >> 5;
    const int lane = tid & 31;
    const int gid = lane >> 2;     // 0..7
    const int tig = lane & 3;      // 0..3
    const int wm = wid >> 1;       // 0..3 -> rows wm*32
    const int wn = wid & 1;        // 0..1 -> cols wn*64
    const int m0 = blockIdx.y * 128;
    const int n0 = blockIdx.x * 128;

    float acc[2][8][4];
    #pragma unroll
    for (int i = 0; i < 2; i++)
        #pragma unroll
        for (int j = 0; j < 8; j++)
            #pragma unroll
            for (int t = 0; t < 4; t++) acc[i][j][t] = 0.0f;

    auto load_tile = [&](int t) {
        float* sa = smem + (t & 1) * STAGE_F;
        float* sb = sa + TILE_F;
        const int k0 = t * 32;
        #pragma unroll
        for (int i = 0; i < 4; i++) {
            int id = i * 256 + tid;
            int row = id >> 3, c4 = (id & 7) * 4;
            cp_async16(sa + row * RS + c4, A + (size_t)(m0 + row) * K + k0 + c4);
        }
        #pragma unroll
        for (int i = 0; i < 4; i++) {
            int id = i * 256 + tid;
            int row = id >> 3, c4 = (id & 7) * 4;
            cp_async16(sb + row * RS + c4, Bt + (size_t)(n0 + row) * K + k0 + c4);
        }
        asm volatile("cp.async.commit_group;\n" ::);
    };

    auto compute = [&](int buf) {
        const float* sa = smem + buf * STAGE_F;
        const float* sb = sa + TILE_F;
        #pragma unroll
        for (int k8 = 0; k8 < 4; k8++) {
            const int kb = k8 * 8;
            uint32_t af[2][4];
            #pragma unroll
            for (int i = 0; i < 2; i++) {
                const int r = wm * 32 + i * 16;
                af[i][0] = f2tf32(sa[(r + gid) * RS + kb + tig]);
                af[i][1] = f2tf32(sa[(r + gid + 8) * RS + kb + tig]);
                af[i][2] = f2tf32(sa[(r + gid) * RS + kb + tig + 4]);
                af[i][3] = f2tf32(sa[(r + gid + 8) * RS + kb + tig + 4]);
            }
            uint32_t bf[8][2];
            #pragma unroll
            for (int j = 0; j < 8; j++) {
                const int n = wn * 64 + j * 8;
                bf[j][0] = f2tf32(sb[(n + gid) * RS + kb + tig]);
                bf[j][1] = f2tf32(sb[(n + gid) * RS + kb + tig + 4]);
            }
            #pragma unroll
            for (int i = 0; i < 2; i++)
                #pragma unroll
                for (int j = 0; j < 8; j++)
                    mma_tf32(acc[i][j], af[i], bf[j]);
        }
    };

    const int nk = K / 32;
    load_tile(0);
    if (nk > 1) load_tile(1);

    for (int s = 0; s < nk; s++) {
        if (s < nk - 1) asm volatile("cp.async.wait_group 1;\n" ::);
        else            asm volatile("cp.async.wait_group 0;\n" ::);
        __syncthreads();
        compute(s & 1);
        __syncthreads();
        if (s + 2 < nk) load_tile(s + 2);
    }

    // epilogue: c layout m16n8 -> thread (gid,tig): rows gid/gid+8, cols tig*2, tig*2+1
    #pragma unroll
    for (int i = 0; i < 2; i++) {
        const int rbase = m0 + wm * 32 + i * 16 + gid;
        #pragma unroll
        for (int j = 0; j < 8; j++) {
            const int col = n0 + wn * 64 + j * 8 + tig * 2;
            float2 v0 = make_float2(acc[i][j][0] * alpha, acc[i][j][1] * alpha);
            float2 v1 = make_float2(acc[i][j][2] * alpha, acc[i][j][3] * alpha);
            *(float2*)(C + (size_t)rbase * N + col) = v0;
            *(float2*)(C + (size_t)(rbase + 8) * N + col) = v1;
        }
    }
}

// ---------------- transpose [R,C] -> [C,R] (32x32 tiles) ---------------------
__global__ void __launch_bounds__(256) transpose_kernel(
    const float* __restrict__ in, float* __restrict__ out,
    int R, int C, size_t sIn, size_t sOut)
{
    __shared__ float t[32][33];
    in  += blockIdx.z * sIn;
    out += blockIdx.z * sOut;
    const int c0 = blockIdx.x * 32, r0 = blockIdx.y * 32;
    const int x = threadIdx.x & 31, y = threadIdx.x >> 5;   // 32x8
    #pragma unroll
    for (int i = 0; i < 32; i += 8)
        t[y + i][x] = in[(size_t)(r0 + y + i) * C + c0 + x];
    __syncthreads();
    #pragma unroll
    for (int i = 0; i < 32; i += 8)
        out[(size_t)(c0 + y + i) * R + r0 + x] = t[x][y + i];
}

// ---------------- reductions -------------------------------------------------
__device__ __forceinline__ float warp_sum(float v) {
    #pragma unroll
    for (int o = 16; o > 0; o >>= 1) v += __shfl_xor_sync(0xFFFFFFFFu, v, o);
    return v;
}
__device__ __forceinline__ float warp_max(float v) {
    #pragma unroll
    for (int o = 16; o > 0; o >>= 1) v = fmaxf(v, __shfl_xor_sync(0xFFFFFFFFu, v, o));
    return v;
}
__device__ __forceinline__ float block_sum(float v, float* sh) {
    __syncthreads();
    int lane = threadIdx.x & 31, w = threadIdx.x >> 5;
    v = warp_sum(v);
    if (lane == 0) sh[w] = v;
    __syncthreads();
    float r = (threadIdx.x < (blockDim.x >> 5)) ? sh[threadIdx.x] : 0.0f;
    if (w == 0) {
        r = warp_sum(r);
        if (lane == 0) sh[0] = r;
    }
    __syncthreads();
    return sh[0];
}
__device__ __forceinline__ float block_max(float v, float* sh) {
    __syncthreads();
    int lane = threadIdx.x & 31, w = threadIdx.x >> 5;
    v = warp_max(v);
    if (lane == 0) sh[w] = v;
    __syncthreads();
    float r = (threadIdx.x < (blockDim.x >> 5)) ? sh[threadIdx.x] : -INFINITY;
    if (w == 0) {
        r = warp_max(r);
        if (lane == 0) sh[0] = r;
    }
    __syncthreads();
    return sh[0];
}

// ---------------- row softmax over S_=2048 cols ------------------------------
__global__ void __launch_bounds__(256) softmax_kernel(float* __restrict__ Sc) {
    __shared__ float sh[32];
    const size_t row = blockIdx.x;
    float* p = Sc + row * (size_t)S_;
    const int tid = threadIdx.x;

    float v[8];
    float mx = -INFINITY;
    #pragma unroll
    for (int i = 0; i < 8; i++) {
        v[i] = p[tid + i * 256];
        mx = fmaxf(mx, v[i]);
    }
    mx = block_max(mx, sh);

    float s = 0.0f;
    #pragma unroll
    for (int i = 0; i < 8; i++) {
        v[i] = __expf(v[i] - mx);
        s += v[i];
    }
    s = block_sum(s, sh);
    const float inv = 1.0f / s;
    #pragma unroll
    for (int i = 0; i < 8; i++) p[tid + i * 256] = v[i] * inv;
}

// ---------------- residual(+bo) + LN + LN, fused -----------------------------
__global__ void __launch_bounds__(256) resid_ln2_kernel(
    const float* __restrict__ src, const float* __restrict__ ao,
    const float* __restrict__ bo,
    const float* __restrict__ w1, const float* __restrict__ b1,
    const float* __restrict__ w2, const float* __restrict__ b2,
    float* __restrict__ xout)
{
    __shared__ float sh[32];
    const size_t row = blockIdx.x;
    const int tid = threadIdx.x;
    const size_t base = row * (size_t)D_;

    float v[3];
    int d[3];
    #pragma unroll
    for (int i = 0; i < 3; i++) {
        d[i] = tid + i * 256;
        v[i] = src[base + d[i]] + ao[base + d[i]] + bo[d[i]];
    }

    float s = v[0] + v[1] + v[2];
    s = block_sum(s, sh);
    const float mu1 = s * (1.0f / (float)D_);
    float sq = 0.0f;
    #pragma unroll
    for (int i = 0; i < 3; i++) { float t = v[i] - mu1; sq += t * t; }
    sq = block_sum(sq, sh);
    const float r1 = rsqrtf(sq * (1.0f / (float)D_) + EPS_);
    #pragma unroll
    for (int i = 0; i < 3; i++)
        v[i] = (v[i] - mu1) * r1 * w1[d[i]] + b1[d[i]];

    s = v[0] + v[1] + v[2];
    s = block_sum(s, sh);
    const float mu2 = s * (1.0f / (float)D_);
    sq = 0.0f;
    #pragma unroll
    for (int i = 0; i < 3; i++) { float t = v[i] - mu2; sq += t * t; }
    sq = block_sum(sq, sh);
    const float r2 = rsqrtf(sq * (1.0f / (float)D_) + EPS_);
    #pragma unroll
    for (int i = 0; i < 3; i++)
        xout[base + d[i]] = (v[i] - mu2) * r2 * w2[d[i]] + b2[d[i]];
}

// ---------------- pooled mean over S ----------------------------------------
__global__ void __launch_bounds__(256) pool_kernel(const float* __restrict__ x,
                                                   float* __restrict__ pooled) {
    const int b = blockIdx.y;
    const int dd = blockIdx.x * 256 + threadIdx.x;
    const float* p = x + (size_t)b * S_ * D_ + dd;
    float s = 0.0f;
    for (int t = 0; t < S_; t++) s += p[(size_t)t * D_];
    pooled[b * D_ + dd] = s * (1.0f / (float)S_);
}

// ---------------- logits -----------------------------------------------------
__global__ void __launch_bounds__(128) logits_kernel(
    const float* __restrict__ pooled, const float* __restrict__ Wc,
    const float* __restrict__ bc, float* __restrict__ out)
{
    __shared__ float sh[32];
    const int idx = blockIdx.x;
    const int b = idx / 10, o = idx % 10;
    float s = 0.0f;
    for (int dd = threadIdx.x; dd < D_; dd += 128)
        s += pooled[b * D_ + dd] * Wc[dd * 10 + o];
    s = block_sum(s, sh);
    if (threadIdx.x == 0) out[b * 10 + o] = s + bc[o];
}

// ---------------- launch -----------------------------------------------------
extern "C" void kernel_launch(void* const* d_in, const int* in_sizes, int n_in,
                              void* d_out, int out_size) {
    const float* src  = (const float*)d_in[0];
    const float* Wq   = (const float*)d_in[1];
    const float* Wk   = (const float*)d_in[2];
    const float* Wv   = (const float*)d_in[3];
    const float* Wo   = (const float*)d_in[4];
    const float* bo   = (const float*)d_in[5];
    const float* ln1w = (const float*)d_in[6];
    const float* ln1b = (const float*)d_in[7];
    const float* ln2w = (const float*)d_in[8];
    const float* ln2b = (const float*)d_in[9];
    const float* Wc   = (const float*)d_in[10];
    const float* bc   = (const float*)d_in[11];

    float* out    = (float*)d_out;
    float* logits = out;           // [8,10]
    float* xout   = out + B_ * 10; // [8,2048,768]

    float *Q, *K, *V, *Vt, *Sc, *ctx, *ao, *pooled;
    float *WqT, *WkT, *WvT, *WoT;
    cudaGetSymbolAddress((void**)&Q,      g_Q);
    cudaGetSymbolAddress((void**)&K,      g_K);
    cudaGetSymbolAddress((void**)&V,      g_V);
    cudaGetSymbolAddress((void**)&Vt,     g_Vt);
    cudaGetSymbolAddress((void**)&Sc,     g_Sc);
    cudaGetSymbolAddress((void**)&ctx,    g_ctx);
    cudaGetSymbolAddress((void**)&ao,     g_ao);
    cudaGetSymbolAddress((void**)&pooled, g_pooled);
    cudaGetSymbolAddress((void**)&WqT,    g_WqT);
    cudaGetSymbolAddress((void**)&WkT,    g_WkT);
    cudaGetSymbolAddress((void**)&WvT,    g_WvT);
    cudaGetSymbolAddress((void**)&WoT,    g_WoT);

    cudaFuncSetAttribute(gemm_mma, cudaFuncAttributeMaxDynamicSharedMemorySize, GEMM_SMEM);

    // 0) transpose weights: W [in,out] -> WT [out,in]
    {
        dim3 grid(DK_ / 32, D_ / 32, 1);
        transpose_kernel<<<grid, 256>>>(Wq, WqT, D_, DK_, 0, 0);
        transpose_kernel<<<grid, 256>>>(Wk, WkT, D_, DK_, 0, 0);
        transpose_kernel<<<grid, 256>>>(Wv, WvT, D_, DK_, 0, 0);
        dim3 grido(D_ / 32, DK_ / 32, 1);
        transpose_kernel<<<grido, 256>>>(Wo, WoT, DK_, D_, 0, 0);
    }
    // 1) Q,K,V = src @ W*
    {
        dim3 grid(DK_ / 128, MTOT / 128, 1);
        gemm_mma<<<grid, 256, GEMM_SMEM>>>(src, WqT, Q, MTOT, DK_, D_, 1.0f, 0, 0, 0);
        gemm_mma<<<grid, 256, GEMM_SMEM>>>(src, WkT, K, MTOT, DK_, D_, 1.0f, 0, 0, 0);
        gemm_mma<<<grid, 256, GEMM_SMEM>>>(src, WvT, V, MTOT, DK_, D_, 1.0f, 0, 0, 0);
    }
    // 2) scores = Q @ K^T * 1/sqrt(DK)
    {
        dim3 grid(S_ / 128, S_ / 128, B_);
        const float alpha = rsqrtf((float)DK_);
        gemm_mma<<<grid, 256, GEMM_SMEM>>>(Q, K, Sc, S_, S_, DK_, alpha,
                                           (size_t)S_ * DK_, (size_t)S_ * DK_,
                                           (size_t)S_ * S_);
    }
    // 3) softmax rows
    softmax_kernel<<<B_ * S_, 256>>>(Sc);
    // 4) V^T per batch: [S,DK] -> [DK,S]
    {
        dim3 grid(DK_ / 32, S_ / 32, B_);
        transpose_kernel<<<grid, 256>>>(V, Vt, S_, DK_,
                                        (size_t)S_ * DK_, (size_t)DK_ * S_);
    }
    // 5) ctx = attn @ V
    {
        dim3 grid(DK_ / 128, S_ / 128, B_);
        gemm_mma<<<grid, 256, GEMM_SMEM>>>(Sc, Vt, ctx, S_, DK_, S_, 1.0f,
                                           (size_t)S_ * S_, (size_t)DK_ * S_,
                                           (size_t)S_ * DK_);
    }
    // 6) ao = ctx @ Wo
    {
        dim3 grid(D_ / 128, MTOT / 128, 1);
        gemm_mma<<<grid, 256, GEMM_SMEM>>>(ctx, WoT, ao, MTOT, D_, DK_, 1.0f, 0, 0, 0);
    }
    // 7) x = LN2(LN1(src + ao + bo))
    resid_ln2_kernel<<<MTOT, 256>>>(src, ao, bo, ln1w, ln1b, ln2w, ln2b, xout);
    // 8) pooled mean over S
    {
        dim3 grid(D_ / 256, B_);
        pool_kernel<<<grid, 256>>>(xout, pooled);
    }
    // 9) logits
    logits_kernel<<<B_ * 10, 128>>>(pooled, Wc, bc, logits);
}

// round 5
// speedup vs baseline: 5.0751x; 1.6138x over previous
#include <cuda_runtime.h>
#include <cuda_fp16.h>
#include <cstdint>
#include <math.h>

#define B_ 8
#define S_ 2048
#define D_ 768
#define DK_ 768
#define MTOT (B_ * S_)   // 16384
#define EPS_ 1e-5f

// ---------------- scratch (device globals; no allocations allowed) ----------
__device__ __align__(16) __half g_srch[(size_t)MTOT * D_];
__device__ __align__(16) __half g_Qh[(size_t)MTOT * DK_];
__device__ __align__(16) __half g_Kh[(size_t)MTOT * DK_];
__device__ __align__(16) __half g_Vh[(size_t)MTOT * DK_];
__device__ __align__(16) __half g_Vth[(size_t)B_ * DK_ * S_];
__device__ float g_Sc[(size_t)B_ * S_ * S_];                  // fp32 scores (134MB)
__device__ __align__(16) __half g_Sch[(size_t)B_ * S_ * S_];  // half probs (67MB)
__device__ __align__(16) __half g_ctxh[(size_t)MTOT * DK_];
__device__ float g_ao[(size_t)MTOT * D_];
__device__ float g_pooled[B_ * D_];
__device__ __align__(16) __half g_WqT[D_ * DK_];
__device__ __align__(16) __half g_WkT[D_ * DK_];
__device__ __align__(16) __half g_WvT[D_ * DK_];
__device__ __align__(16) __half g_WoT[DK_ * D_];

// ---------------- helpers ----------------------------------------------------
__device__ __forceinline__ void cp_async16(void* sp, const void* gp) {
    unsigned s = (unsigned)__cvta_generic_to_shared(sp);
    asm volatile("cp.async.cg.shared.global [%0], [%1], 16;\n" :: "r"(s), "l"(gp));
}
__device__ __forceinline__ void mma_f16(float* d, const uint32_t* a, const uint32_t* b) {
    asm volatile(
        "mma.sync.aligned.m16n8k16.row.col.f32.f16.f16.f32 "
        "{%0,%1,%2,%3}, {%4,%5,%6,%7}, {%8,%9}, {%0,%1,%2,%3};"
        : "+f"(d[0]), "+f"(d[1]), "+f"(d[2]), "+f"(d[3])
        : "r"(a[0]), "r"(a[1]), "r"(a[2]), "r"(a[3]), "r"(b[0]), "r"(b[1]));
}

// ---------------- FP16 mma.sync GEMM: C[M,N] = alpha * A[M,K] @ Bt[N,K]^T ----
// A, Bt are half (K-major). 128x128 CTA tile, BK=32, double-buffered cp.async,
// 8 warps (4Mx2N), warp tile 32x64. fp32 accumulate. HALF_OUT: C stored half.
#define RS_H 40                        // smem row stride in halves
#define TILE_H (128 * RS_H)            // halves per matrix tile
#define STAGE_H (2 * TILE_H)           // A + B

template <bool HALF_OUT>
__global__ void __launch_bounds__(256, 2) gemm_h(
    const __half* __restrict__ A, const __half* __restrict__ Bt,
    void* __restrict__ Cv, int M, int N, int K, float alpha,
    size_t sA, size_t sB, size_t sC)
{
    __shared__ __half smem[2 * STAGE_H];   // 40 KB

    A  += blockIdx.z * sA;
    Bt += blockIdx.z * sB;

    const int tid = threadIdx.x;
    const int wid = tid >> 5;
    const int lane = tid & 31;
    const int gid = lane >> 2;     // 0..7
    const int tig = lane & 3;      // 0..3
    const int wm = wid >> 1;       // 0..3 -> rows wm*32
    const int wn = wid & 1;        // 0..1 -> cols wn*64
    const int m0 = blockIdx.y * 128;
    const int n0 = blockIdx.x * 128;

    float acc[2][8][4];
    #pragma unroll
    for (int i = 0; i < 2; i++)
        #pragma unroll
        for (int j = 0; j < 8; j++)
            #pragma unroll
            for (int t = 0; t < 4; t++) acc[i][j][t] = 0.0f;

    auto load_tile = [&](int t) {
        __half* sa = smem + (t & 1) * STAGE_H;
        __half* sb = sa + TILE_H;
        const int k0 = t * 32;
        #pragma unroll
        for (int i = 0; i < 2; i++) {
            int id = i * 256 + tid;
            int row = id >> 2, c8 = (id & 3) * 8;
            cp_async16(sa + row * RS_H + c8, A + (size_t)(m0 + row) * K + k0 + c8);
        }
        #pragma unroll
        for (int i = 0; i < 2; i++) {
            int id = i * 256 + tid;
            int row = id >> 2, c8 = (id & 3) * 8;
            cp_async16(sb + row * RS_H + c8, Bt + (size_t)(n0 + row) * K + k0 + c8);
        }
        asm volatile("cp.async.commit_group;\n" ::);
    };

    auto compute = [&](int buf) {
        const __half* sa = smem + buf * STAGE_H;
        const __half* sb = sa + TILE_H;
        #pragma unroll
        for (int k16 = 0; k16 < 2; k16++) {
            const int kb = k16 * 16;
            uint32_t af[2][4];
            #pragma unroll
            for (int i = 0; i < 2; i++) {
                const int r = wm * 32 + i * 16;
                af[i][0] = *(const uint32_t*)&sa[(r + gid) * RS_H + kb + 2 * tig];
                af[i][1] = *(const uint32_t*)&sa[(r + gid + 8) * RS_H + kb + 2 * tig];
                af[i][2] = *(const uint32_t*)&sa[(r + gid) * RS_H + kb + 2 * tig + 8];
                af[i][3] = *(const uint32_t*)&sa[(r + gid + 8) * RS_H + kb + 2 * tig + 8];
            }
            uint32_t bf[8][2];
            #pragma unroll
            for (int j = 0; j < 8; j++) {
                const int n = wn * 64 + j * 8;
                bf[j][0] = *(const uint32_t*)&sb[(n + gid) * RS_H + kb + 2 * tig];
                bf[j][1] = *(const uint32_t*)&sb[(n + gid) * RS_H + kb + 2 * tig + 8];
            }
            #pragma unroll
            for (int i = 0; i < 2; i++)
                #pragma unroll
                for (int j = 0; j < 8; j++)
                    mma_f16(acc[i][j], af[i], bf[j]);
        }
    };

    const int nk = K / 32;
    load_tile(0);
    if (nk > 1) load_tile(1);

    for (int s = 0; s < nk; s++) {
        if (s < nk - 1) asm volatile("cp.async.wait_group 1;\n" ::);
        else            asm volatile("cp.async.wait_group 0;\n" ::);
        __syncthreads();
        compute(s & 1);
        __syncthreads();
        if (s + 2 < nk) load_tile(s + 2);
    }

    // epilogue
    if (HALF_OUT) {
        __half* C = (__half*)Cv + blockIdx.z * sC;
        #pragma unroll
        for (int i = 0; i < 2; i++) {
            const int rbase = m0 + wm * 32 + i * 16 + gid;
            #pragma unroll
            for (int j = 0; j < 8; j++) {
                const int col = n0 + wn * 64 + j * 8 + tig * 2;
                *(__half2*)(C + (size_t)rbase * N + col) =
                    __floats2half2_rn(acc[i][j][0] * alpha, acc[i][j][1] * alpha);
                *(__half2*)(C + (size_t)(rbase + 8) * N + col) =
                    __floats2half2_rn(acc[i][j][2] * alpha, acc[i][j][3] * alpha);
            }
        }
    } else {
        float* C = (float*)Cv + blockIdx.z * sC;
        #pragma unroll
        for (int i = 0; i < 2; i++) {
            const int rbase = m0 + wm * 32 + i * 16 + gid;
            #pragma unroll
            for (int j = 0; j < 8; j++) {
                const int col = n0 + wn * 64 + j * 8 + tig * 2;
                *(float2*)(C + (size_t)rbase * N + col) =
                    make_float2(acc[i][j][0] * alpha, acc[i][j][1] * alpha);
                *(float2*)(C + (size_t)(rbase + 8) * N + col) =
                    make_float2(acc[i][j][2] * alpha, acc[i][j][3] * alpha);
            }
        }
    }
}

// ---------------- conversions / transposes -----------------------------------
__global__ void __launch_bounds__(256) f2h_kernel(const float* __restrict__ in,
                                                  __half* __restrict__ out, int n4) {
    int i = blockIdx.x * 256 + threadIdx.x;
    if (i < n4) {
        float4 v = ((const float4*)in)[i];
        ((__half2*)out)[2 * i]     = __floats2half2_rn(v.x, v.y);
        ((__half2*)out)[2 * i + 1] = __floats2half2_rn(v.z, v.w);
    }
}

// fp32 in [R,C] -> half out [C,R]
__global__ void __launch_bounds__(256) transpose_f2h(
    const float* __restrict__ in, __half* __restrict__ out, int R, int C)
{
    __shared__ float t[32][33];
    const int c0 = blockIdx.x * 32, r0 = blockIdx.y * 32;
    const int x = threadIdx.x & 31, y = threadIdx.x >> 5;
    #pragma unroll
    for (int i = 0; i < 32; i += 8)
        t[y + i][x] = in[(size_t)(r0 + y + i) * C + c0 + x];
    __syncthreads();
    #pragma unroll
    for (int i = 0; i < 32; i += 8)
        out[(size_t)(c0 + y + i) * R + r0 + x] = __float2half(t[x][y + i]);
}

// half in [R,C] -> half out [C,R], batched
__global__ void __launch_bounds__(256) transpose_h2h(
    const __half* __restrict__ in, __half* __restrict__ out,
    int R, int C, size_t sIn, size_t sOut)
{
    __shared__ __half t[32][34];
    in  += blockIdx.z * sIn;
    out += blockIdx.z * sOut;
    const int c0 = blockIdx.x * 32, r0 = blockIdx.y * 32;
    const int x = threadIdx.x & 31, y = threadIdx.x >> 5;
    #pragma unroll
    for (int i = 0; i < 32; i += 8)
        t[y + i][x] = in[(size_t)(r0 + y + i) * C + c0 + x];
    __syncthreads();
    #pragma unroll
    for (int i = 0; i < 32; i += 8)
        out[(size_t)(c0 + y + i) * R + r0 + x] = t[x][y + i];
}

// ---------------- reductions -------------------------------------------------
__device__ __forceinline__ float warp_sum(float v) {
    #pragma unroll
    for (int o = 16; o > 0; o >>= 1) v += __shfl_xor_sync(0xFFFFFFFFu, v, o);
    return v;
}
__device__ __forceinline__ float warp_max(float v) {
    #pragma unroll
    for (int o = 16; o > 0; o >>= 1) v = fmaxf(v, __shfl_xor_sync(0xFFFFFFFFu, v, o));
    return v;
}
__device__ __forceinline__ float block_sum(float v, float* sh) {
    __syncthreads();
    int lane = threadIdx.x & 31, w = threadIdx.x >> 5;
    v = warp_sum(v);
    if (lane == 0) sh[w] = v;
    __syncthreads();
    float r = (threadIdx.x < (blockDim.x >> 5)) ? sh[threadIdx.x] : 0.0f;
    if (w == 0) {
        r = warp_sum(r);
        if (lane == 0) sh[0] = r;
    }
    __syncthreads();
    return sh[0];
}
__device__ __forceinline__ float block_max(float v, float* sh) {
    __syncthreads();
    int lane = threadIdx.x & 31, w = threadIdx.x >> 5;
    v = warp_max(v);
    if (lane == 0) sh[w] = v;
    __syncthreads();
    float r = (threadIdx.x < (blockDim.x >> 5)) ? sh[threadIdx.x] : -INFINITY;
    if (w == 0) {
        r = warp_max(r);
        if (lane == 0) sh[0] = r;
    }
    __syncthreads();
    return sh[0];
}

// ---------------- row softmax fp32 -> half probs ------------------------------
__global__ void __launch_bounds__(256) softmax_kernel(const float* __restrict__ Sc,
                                                      __half* __restrict__ Pr) {
    __shared__ float sh[32];
    const size_t row = blockIdx.x;
    const float* p = Sc + row * (size_t)S_;
    __half* q = Pr + row * (size_t)S_;
    const int tid = threadIdx.x;

    float v[8];
    float mx = -INFINITY;
    #pragma unroll
    for (int i = 0; i < 8; i++) {
        v[i] = p[tid + i * 256];
        mx = fmaxf(mx, v[i]);
    }
    mx = block_max(mx, sh);

    float s = 0.0f;
    #pragma unroll
    for (int i = 0; i < 8; i++) {
        v[i] = __expf(v[i] - mx);
        s += v[i];
    }
    s = block_sum(s, sh);
    const float inv = 1.0f / s;
    #pragma unroll
    for (int i = 0; i < 8; i++) q[tid + i * 256] = __float2half(v[i] * inv);
}

// ---------------- residual(+bo) + LN + LN, fused -----------------------------
__global__ void __launch_bounds__(256) resid_ln2_kernel(
    const float* __restrict__ src, const float* __restrict__ ao,
    const float* __restrict__ bo,
    const float* __restrict__ w1, const float* __restrict__ b1,
    const float* __restrict__ w2, const float* __restrict__ b2,
    float* __restrict__ xout)
{
    __shared__ float sh[32];
    const size_t row = blockIdx.x;
    const int tid = threadIdx.x;
    const size_t base = row * (size_t)D_;

    float v[3];
    int d[3];
    #pragma unroll
    for (int i = 0; i < 3; i++) {
        d[i] = tid + i * 256;
        v[i] = src[base + d[i]] + ao[base + d[i]] + bo[d[i]];
    }

    float s = v[0] + v[1] + v[2];
    s = block_sum(s, sh);
    const float mu1 = s * (1.0f / (float)D_);
    float sq = 0.0f;
    #pragma unroll
    for (int i = 0; i < 3; i++) { float t = v[i] - mu1; sq += t * t; }
    sq = block_sum(sq, sh);
    const float r1 = rsqrtf(sq * (1.0f / (float)D_) + EPS_);
    #pragma unroll
    for (int i = 0; i < 3; i++)
        v[i] = (v[i] - mu1) * r1 * w1[d[i]] + b1[d[i]];

    s = v[0] + v[1] + v[2];
    s = block_sum(s, sh);
    const float mu2 = s * (1.0f / (float)D_);
    sq = 0.0f;
    #pragma unroll
    for (int i = 0; i < 3; i++) { float t = v[i] - mu2; sq += t * t; }
    sq = block_sum(sq, sh);
    const float r2 = rsqrtf(sq * (1.0f / (float)D_) + EPS_);
    #pragma unroll
    for (int i = 0; i < 3; i++)
        xout[base + d[i]] = (v[i] - mu2) * r2 * w2[d[i]] + b2[d[i]];
}

// ---------------- pooled mean over S ----------------------------------------
__global__ void __launch_bounds__(256) pool_kernel(const float* __restrict__ x,
                                                   float* __restrict__ pooled) {
    const int b = blockIdx.y;
    const int dd = blockIdx.x * 256 + threadIdx.x;
    const float* p = x + (size_t)b * S_ * D_ + dd;
    float s = 0.0f;
    for (int t = 0; t < S_; t++) s += p[(size_t)t * D_];
    pooled[b * D_ + dd] = s * (1.0f / (float)S_);
}

// ---------------- logits -----------------------------------------------------
__global__ void __launch_bounds__(128) logits_kernel(
    const float* __restrict__ pooled, const float* __restrict__ Wc,
    const float* __restrict__ bc, float* __restrict__ out)
{
    __shared__ float sh[32];
    const int idx = blockIdx.x;
    const int b = idx / 10, o = idx % 10;
    float s = 0.0f;
    for (int dd = threadIdx.x; dd < D_; dd += 128)
        s += pooled[b * D_ + dd] * Wc[dd * 10 + o];
    s = block_sum(s, sh);
    if (threadIdx.x == 0) out[b * 10 + o] = s + bc[o];
}

// ---------------- launch -----------------------------------------------------
extern "C" void kernel_launch(void* const* d_in, const int* in_sizes, int n_in,
                              void* d_out, int out_size) {
    const float* src  = (const float*)d_in[0];
    const float* Wq   = (const float*)d_in[1];
    const float* Wk   = (const float*)d_in[2];
    const float* Wv   = (const float*)d_in[3];
    const float* Wo   = (const float*)d_in[4];
    const float* bo   = (const float*)d_in[5];
    const float* ln1w = (const float*)d_in[6];
    const float* ln1b = (const float*)d_in[7];
    const float* ln2w = (const float*)d_in[8];
    const float* ln2b = (const float*)d_in[9];
    const float* Wc   = (const float*)d_in[10];
    const float* bc   = (const float*)d_in[11];

    float* out    = (float*)d_out;
    float* logits = out;           // [8,10]
    float* xout   = out + B_ * 10; // [8,2048,768]

    __half *srch, *Qh, *Kh, *Vh, *Vth, *Sch, *ctxh, *WqT, *WkT, *WvT, *WoT;
    float *Sc, *ao, *pooled;
    cudaGetSymbolAddress((void**)&srch,   g_srch);
    cudaGetSymbolAddress((void**)&Qh,     g_Qh);
    cudaGetSymbolAddress((void**)&Kh,     g_Kh);
    cudaGetSymbolAddress((void**)&Vh,     g_Vh);
    cudaGetSymbolAddress((void**)&Vth,    g_Vth);
    cudaGetSymbolAddress((void**)&Sc,     g_Sc);
    cudaGetSymbolAddress((void**)&Sch,    g_Sch);
    cudaGetSymbolAddress((void**)&ctxh,   g_ctxh);
    cudaGetSymbolAddress((void**)&ao,     g_ao);
    cudaGetSymbolAddress((void**)&pooled, g_pooled);
    cudaGetSymbolAddress((void**)&WqT,    g_WqT);
    cudaGetSymbolAddress((void**)&WkT,    g_WkT);
    cudaGetSymbolAddress((void**)&WvT,    g_WvT);
    cudaGetSymbolAddress((void**)&WoT,    g_WoT);

    // 0) src -> half; weights -> transposed half
    f2h_kernel<<<(MTOT * D_ / 4 + 255) / 256, 256>>>(src, srch, MTOT * D_ / 4);
    {
        dim3 grid(DK_ / 32, D_ / 32);
        transpose_f2h<<<grid, 256>>>(Wq, WqT, D_, DK_);
        transpose_f2h<<<grid, 256>>>(Wk, WkT, D_, DK_);
        transpose_f2h<<<grid, 256>>>(Wv, WvT, D_, DK_);
        dim3 grido(D_ / 32, DK_ / 32);
        transpose_f2h<<<grido, 256>>>(Wo, WoT, DK_, D_);
    }
    // 1) Q,K,V = src @ W*  (half out)
    {
        dim3 grid(DK_ / 128, MTOT / 128, 1);
        gemm_h<true><<<grid, 256>>>(srch, WqT, Qh, MTOT, DK_, D_, 1.0f, 0, 0, 0);
        gemm_h<true><<<grid, 256>>>(srch, WkT, Kh, MTOT, DK_, D_, 1.0f, 0, 0, 0);
        gemm_h<true><<<grid, 256>>>(srch, WvT, Vh, MTOT, DK_, D_, 1.0f, 0, 0, 0);
    }
    // 2) scores = Q @ K^T * 1/sqrt(DK)  (fp32 out)
    {
        dim3 grid(S_ / 128, S_ / 128, B_);
        const float alpha = rsqrtf((float)DK_);
        gemm_h<false><<<grid, 256>>>(Qh, Kh, Sc, S_, S_, DK_, alpha,
                                     (size_t)S_ * DK_, (size_t)S_ * DK_,
                                     (size_t)S_ * S_);
    }
    // 3) softmax rows -> half probs
    softmax_kernel<<<B_ * S_, 256>>>(Sc, Sch);
    // 4) V^T per batch (half)
    {
        dim3 grid(DK_ / 32, S_ / 32, B_);
        transpose_h2h<<<grid, 256>>>(Vh, Vth, S_, DK_,
                                     (size_t)S_ * DK_, (size_t)DK_ * S_);
    }
    // 5) ctx = probs @ V  (half out)
    {
        dim3 grid(DK_ / 128, S_ / 128, B_);
        gemm_h<true><<<grid, 256>>>(Sch, Vth, ctxh, S_, DK_, S_, 1.0f,
                                    (size_t)S_ * S_, (size_t)DK_ * S_,
                                    (size_t)S_ * DK_);
    }
    // 6) ao = ctx @ Wo  (fp32 out; bo folded into resid kernel)
    {
        dim3 grid(D_ / 128, MTOT / 128, 1);
        gemm_h<false><<<grid, 256>>>(ctxh, WoT, ao, MTOT, D_, DK_, 1.0f, 0, 0, 0);
    }
    // 7) x = LN2(LN1(src + ao + bo))
    resid_ln2_kernel<<<MTOT, 256>>>(src, ao, bo, ln1w, ln1b, ln2w, ln2b, xout);
    // 8) pooled mean over S
    {
        dim3 grid(D_ / 256, B_);
        pool_kernel<<<grid, 256>>>(xout, pooled);
    }
    // 9) logits
    logits_kernel<<<B_ * 10, 128>>>(pooled, Wc, bc, logits);
}

// round 6
// speedup vs baseline: 5.8185x; 1.1465x over previous
#include <cuda_runtime.h>
#include <cuda_fp16.h>
#include <cstdint>
#include <math.h>

#define B_ 8
#define S_ 2048
#define D_ 768
#define DK_ 768
#define MTOT (B_ * S_)   // 16384
#define EPS_ 1e-5f

// ---------------- scratch (device globals; no allocations allowed) ----------
__device__ __align__(16) __half g_srch[(size_t)MTOT * D_];
__device__ __align__(16) __half g_Qh[(size_t)MTOT * DK_];
__device__ __align__(16) __half g_Kh[(size_t)MTOT * DK_];
__device__ __align__(16) __half g_Vh[(size_t)MTOT * DK_];
__device__ __align__(16) __half g_Sch[(size_t)B_ * S_ * S_];  // scores->probs fp16
__device__ __align__(16) __half g_ctxh[(size_t)MTOT * DK_];
__device__ float g_ao[(size_t)MTOT * D_];
__device__ float g_pooled[B_ * D_];
__device__ __align__(16) __half g_Wqh[D_ * DK_];   // [K,N] native layout
__device__ __align__(16) __half g_Wkh[D_ * DK_];
__device__ __align__(16) __half g_Wvh[D_ * DK_];
__device__ __align__(16) __half g_Woh[DK_ * D_];

// ---------------- helpers ----------------------------------------------------
__device__ __forceinline__ void cp_async16(void* sp, const void* gp) {
    unsigned s = (unsigned)__cvta_generic_to_shared(sp);
    asm volatile("cp.async.cg.shared.global [%0], [%1], 16;\n" :: "r"(s), "l"(gp));
}
__device__ __forceinline__ void mma_f16(float* d, const uint32_t* a, const uint32_t* b) {
    asm volatile(
        "mma.sync.aligned.m16n8k16.row.col.f32.f16.f16.f32 "
        "{%0,%1,%2,%3}, {%4,%5,%6,%7}, {%8,%9}, {%0,%1,%2,%3};"
        : "+f"(d[0]), "+f"(d[1]), "+f"(d[2]), "+f"(d[3])
        : "r"(a[0]), "r"(a[1]), "r"(a[2]), "r"(a[3]), "r"(b[0]), "r"(b[1]));
}
__device__ __forceinline__ void ldsm_x4(uint32_t& r0, uint32_t& r1, uint32_t& r2,
                                        uint32_t& r3, uint32_t addr) {
    asm volatile("ldmatrix.sync.aligned.m8n8.x4.shared.b16 {%0,%1,%2,%3}, [%4];"
                 : "=r"(r0), "=r"(r1), "=r"(r2), "=r"(r3) : "r"(addr));
}
__device__ __forceinline__ void ldsm_x4_t(uint32_t& r0, uint32_t& r1, uint32_t& r2,
                                          uint32_t& r3, uint32_t addr) {
    asm volatile("ldmatrix.sync.aligned.m8n8.x4.trans.shared.b16 {%0,%1,%2,%3}, [%4];"
                 : "=r"(r0), "=r"(r1), "=r"(r2), "=r"(r3) : "r"(addr));
}

// ---------------- FP16 mma.sync GEMM -----------------------------------------
// C[M,N] = alpha * A[M,K] @ B, A half K-major.
// BMODE 0: B is [N,K] (K-major, e.g. K-matrix for scores)
// BMODE 1: B is [K,N] (native weights / V / ctx@Wo), loaded via ldmatrix.trans
// 128x128 CTA tile, BK=32, double-buffered cp.async, 8 warps (4Mx2N), warp 32x64.
#define RS_A 40                          // A / K-major B row stride (halves)
#define RS_BT 136                        // [K,N] B row stride (halves)
#define A_TILE_H (128 * RS_A)            // 5120 halves
#define B_TILE_H (128 * RS_A)            // max(5120, 32*136=4352)
#define STAGE_H (A_TILE_H + B_TILE_H)

template <int BMODE, bool HALF_OUT>
__global__ void __launch_bounds__(256, 2) gemm_h(
    const __half* __restrict__ A, const __half* __restrict__ Bm,
    void* __restrict__ Cv, int M, int N, int K, int ldB, float alpha,
    size_t sA, size_t sB, size_t sC)
{
    __shared__ __half smem[2 * STAGE_H];   // 40 KB

    A  += blockIdx.z * sA;
    Bm += blockIdx.z * sB;

    const int tid = threadIdx.x;
    const int wid = tid >> 5;
    const int lane = tid & 31;
    const int gid = lane >> 2;     // 0..7
    const int tig = lane & 3;      // 0..3
    const int mat = lane >> 3;     // 0..3 (ldmatrix address group)
    const int rw = lane & 7;       // row within 8x8 mat
    const int wm = wid >> 1;       // 0..3 -> rows wm*32
    const int wn = wid & 1;        // 0..1 -> cols wn*64
    const int m0 = blockIdx.y * 128;
    const int n0 = blockIdx.x * 128;

    const uint32_t smem_base = (uint32_t)__cvta_generic_to_shared(smem);

    float acc[2][8][4];
    #pragma unroll
    for (int i = 0; i < 2; i++)
        #pragma unroll
        for (int j = 0; j < 8; j++)
            #pragma unroll
            for (int t = 0; t < 4; t++) acc[i][j][t] = 0.0f;

    auto load_tile = [&](int t) {
        __half* sa = smem + (t & 1) * STAGE_H;
        __half* sb = sa + A_TILE_H;
        const int k0 = t * 32;
        // A: 128 rows x 32 halves = 512 x 16B chunks (4/row)
        #pragma unroll
        for (int i = 0; i < 2; i++) {
            int id = i * 256 + tid;
            int row = id >> 2, c8 = (id & 3) * 8;
            cp_async16(sa + row * RS_A + c8, A + (size_t)(m0 + row) * K + k0 + c8);
        }
        if (BMODE == 0) {
            #pragma unroll
            for (int i = 0; i < 2; i++) {
                int id = i * 256 + tid;
                int row = id >> 2, c8 = (id & 3) * 8;
                cp_async16(sb + row * RS_A + c8, Bm + (size_t)(n0 + row) * ldB + k0 + c8);
            }
        } else {
            // B: 32 rows x 128 halves = 512 x 16B chunks (16/row)
            #pragma unroll
            for (int i = 0; i < 2; i++) {
                int id = i * 256 + tid;
                int row = id >> 4, c8 = (id & 15) * 8;
                cp_async16(sb + row * RS_BT + c8, Bm + (size_t)(k0 + row) * ldB + n0 + c8);
            }
        }
        asm volatile("cp.async.commit_group;\n" ::);
    };

    auto compute = [&](int buf) {
        const uint32_t sa = smem_base + (uint32_t)(buf * STAGE_H) * 2u;
        const uint32_t sb = sa + A_TILE_H * 2u;
        #pragma unroll
        for (int k16 = 0; k16 < 2; k16++) {
            const int kb = k16 * 16;
            uint32_t af[2][4];
            #pragma unroll
            for (int i = 0; i < 2; i++) {
                // a0:(m+rw,kb) a1:(m+8+rw,kb) a2:(m+rw,kb+8) a3:(m+8+rw,kb+8)
                uint32_t addr = sa + 2u * ((wm * 32 + i * 16 + (mat & 1) * 8 + rw) * RS_A
                                           + kb + (mat >> 1) * 8);
                ldsm_x4(af[i][0], af[i][1], af[i][2], af[i][3], addr);
            }
            uint32_t bf[8][2];
            #pragma unroll
            for (int jp = 0; jp < 4; jp++) {
                const int n = wn * 64 + jp * 16;
                if (BMODE == 0) {
                    // b0(j):(n+rw,kb) b1(j):(n+rw,kb+8) b0(j+1):(n+8+rw,kb) b1(j+1):(n+8+rw,kb+8)
                    uint32_t addr = sb + 2u * ((n + (mat >> 1) * 8 + rw) * RS_A
                                               + kb + (mat & 1) * 8);
                    ldsm_x4(bf[2 * jp][0], bf[2 * jp][1], bf[2 * jp + 1][0],
                            bf[2 * jp + 1][1], addr);
                } else {
                    // trans: b0(j):(kb+rw,n) b1(j):(kb+8+rw,n) b0(j+1):(kb+rw,n+8) ...
                    uint32_t addr = sb + 2u * ((kb + (mat & 1) * 8 + rw) * RS_BT
                                               + n + (mat >> 1) * 8);
                    ldsm_x4_t(bf[2 * jp][0], bf[2 * jp][1], bf[2 * jp + 1][0],
                              bf[2 * jp + 1][1], addr);
                }
            }
            #pragma unroll
            for (int i = 0; i < 2; i++)
                #pragma unroll
                for (int j = 0; j < 8; j++)
                    mma_f16(acc[i][j], af[i], bf[j]);
        }
    };

    const int nk = K / 32;
    load_tile(0);
    if (nk > 1) load_tile(1);

    for (int s = 0; s < nk; s++) {
        if (s < nk - 1) asm volatile("cp.async.wait_group 1;\n" ::);
        else            asm volatile("cp.async.wait_group 0;\n" ::);
        __syncthreads();
        compute(s & 1);
        __syncthreads();
        if (s + 2 < nk) load_tile(s + 2);
    }

    // epilogue
    if (HALF_OUT) {
        __half* C = (__half*)Cv + blockIdx.z * sC;
        #pragma unroll
        for (int i = 0; i < 2; i++) {
            const int rbase = m0 + wm * 32 + i * 16 + gid;
            #pragma unroll
            for (int j = 0; j < 8; j++) {
                const int col = n0 + wn * 64 + j * 8 + tig * 2;
                *(__half2*)(C + (size_t)rbase * N + col) =
                    __floats2half2_rn(acc[i][j][0] * alpha, acc[i][j][1] * alpha);
                *(__half2*)(C + (size_t)(rbase + 8) * N + col) =
                    __floats2half2_rn(acc[i][j][2] * alpha, acc[i][j][3] * alpha);
            }
        }
    } else {
        float* C = (float*)Cv + blockIdx.z * sC;
        #pragma unroll
        for (int i = 0; i < 2; i++) {
            const int rbase = m0 + wm * 32 + i * 16 + gid;
            #pragma unroll
            for (int j = 0; j < 8; j++) {
                const int col = n0 + wn * 64 + j * 8 + tig * 2;
                *(float2*)(C + (size_t)rbase * N + col) =
                    make_float2(acc[i][j][0] * alpha, acc[i][j][1] * alpha);
                *(float2*)(C + (size_t)(rbase + 8) * N + col) =
                    make_float2(acc[i][j][2] * alpha, acc[i][j][3] * alpha);
            }
        }
    }
}

// ---------------- fp32 -> fp16 ------------------------------------------------
__global__ void __launch_bounds__(256) f2h_kernel(const float* __restrict__ in,
                                                  __half* __restrict__ out, int n4) {
    int i = blockIdx.x * 256 + threadIdx.x;
    if (i < n4) {
        float4 v = ((const float4*)in)[i];
        ((__half2*)out)[2 * i]     = __floats2half2_rn(v.x, v.y);
        ((__half2*)out)[2 * i + 1] = __floats2half2_rn(v.z, v.w);
    }
}

// ---------------- reductions -------------------------------------------------
__device__ __forceinline__ float warp_sum(float v) {
    #pragma unroll
    for (int o = 16; o > 0; o >>= 1) v += __shfl_xor_sync(0xFFFFFFFFu, v, o);
    return v;
}
__device__ __forceinline__ float warp_max(float v) {
    #pragma unroll
    for (int o = 16; o > 0; o >>= 1) v = fmaxf(v, __shfl_xor_sync(0xFFFFFFFFu, v, o));
    return v;
}
__device__ __forceinline__ float block_sum(float v, float* sh) {
    __syncthreads();
    int lane = threadIdx.x & 31, w = threadIdx.x >> 5;
    v = warp_sum(v);
    if (lane == 0) sh[w] = v;
    __syncthreads();
    float r = (threadIdx.x < (blockDim.x >> 5)) ? sh[threadIdx.x] : 0.0f;
    if (w == 0) {
        r = warp_sum(r);
        if (lane == 0) sh[0] = r;
    }
    __syncthreads();
    return sh[0];
}
__device__ __forceinline__ float block_max(float v, float* sh) {
    __syncthreads();
    int lane = threadIdx.x & 31, w = threadIdx.x >> 5;
    v = warp_max(v);
    if (lane == 0) sh[w] = v;
    __syncthreads();
    float r = (threadIdx.x < (blockDim.x >> 5)) ? sh[threadIdx.x] : -INFINITY;
    if (w == 0) {
        r = warp_max(r);
        if (lane == 0) sh[0] = r;
    }
    __syncthreads();
    return sh[0];
}

// ---------------- row softmax fp16 in-place ----------------------------------
__global__ void __launch_bounds__(256) softmax_kernel(__half* __restrict__ Sc) {
    __shared__ float sh[32];
    const size_t row = blockIdx.x;
    __half2* p = (__half2*)(Sc + row * (size_t)S_);
    const int tid = threadIdx.x;

    float2 v[4];
    float mx = -INFINITY;
    #pragma unroll
    for (int i = 0; i < 4; i++) {
        v[i] = __half22float2(p[tid + i * 256]);
        mx = fmaxf(mx, fmaxf(v[i].x, v[i].y));
    }
    mx = block_max(mx, sh);

    float s = 0.0f;
    #pragma unroll
    for (int i = 0; i < 4; i++) {
        v[i].x = __expf(v[i].x - mx);
        v[i].y = __expf(v[i].y - mx);
        s += v[i].x + v[i].y;
    }
    s = block_sum(s, sh);
    const float inv = 1.0f / s;
    #pragma unroll
    for (int i = 0; i < 4; i++)
        p[tid + i * 256] = __floats2half2_rn(v[i].x * inv, v[i].y * inv);
}

// ---------------- residual(+bo) + LN + LN, fused -----------------------------
__global__ void __launch_bounds__(256) resid_ln2_kernel(
    const float* __restrict__ src, const float* __restrict__ ao,
    const float* __restrict__ bo,
    const float* __restrict__ w1, const float* __restrict__ b1,
    const float* __restrict__ w2, const float* __restrict__ b2,
    float* __restrict__ xout)
{
    __shared__ float sh[32];
    const size_t row = blockIdx.x;
    const int tid = threadIdx.x;
    const size_t base = row * (size_t)D_;

    float v[3];
    int d[3];
    #pragma unroll
    for (int i = 0; i < 3; i++) {
        d[i] = tid + i * 256;
        v[i] = src[base + d[i]] + ao[base + d[i]] + bo[d[i]];
    }

    float s = v[0] + v[1] + v[2];
    s = block_sum(s, sh);
    const float mu1 = s * (1.0f / (float)D_);
    float sq = 0.0f;
    #pragma unroll
    for (int i = 0; i < 3; i++) { float t = v[i] - mu1; sq += t * t; }
    sq = block_sum(sq, sh);
    const float r1 = rsqrtf(sq * (1.0f / (float)D_) + EPS_);
    #pragma unroll
    for (int i = 0; i < 3; i++)
        v[i] = (v[i] - mu1) * r1 * w1[d[i]] + b1[d[i]];

    s = v[0] + v[1] + v[2];
    s = block_sum(s, sh);
    const float mu2 = s * (1.0f / (float)D_);
    sq = 0.0f;
    #pragma unroll
    for (int i = 0; i < 3; i++) { float t = v[i] - mu2; sq += t * t; }
    sq = block_sum(sq, sh);
    const float r2 = rsqrtf(sq * (1.0f / (float)D_) + EPS_);
    #pragma unroll
    for (int i = 0; i < 3; i++)
        xout[base + d[i]] = (v[i] - mu2) * r2 * w2[d[i]] + b2[d[i]];
}

// ---------------- pooled mean over S ----------------------------------------
__global__ void __launch_bounds__(256) pool_kernel(const float* __restrict__ x,
                                                   float* __restrict__ pooled) {
    const int b = blockIdx.y;
    const int dd = blockIdx.x * 256 + threadIdx.x;
    const float* p = x + (size_t)b * S_ * D_ + dd;
    float s = 0.0f;
    for (int t = 0; t < S_; t++) s += p[(size_t)t * D_];
    pooled[b * D_ + dd] = s * (1.0f / (float)S_);
}

// ---------------- logits -----------------------------------------------------
__global__ void __launch_bounds__(128) logits_kernel(
    const float* __restrict__ pooled, const float* __restrict__ Wc,
    const float* __restrict__ bc, float* __restrict__ out)
{
    __shared__ float sh[32];
    const int idx = blockIdx.x;
    const int b = idx / 10, o = idx % 10;
    float s = 0.0f;
    for (int dd = threadIdx.x; dd < D_; dd += 128)
        s += pooled[b * D_ + dd] * Wc[dd * 10 + o];
    s = block_sum(s, sh);
    if (threadIdx.x == 0) out[b * 10 + o] = s + bc[o];
}

// ---------------- launch -----------------------------------------------------
extern "C" void kernel_launch(void* const* d_in, const int* in_sizes, int n_in,
                              void* d_out, int out_size) {
    const float* src  = (const float*)d_in[0];
    const float* Wq   = (const float*)d_in[1];
    const float* Wk   = (const float*)d_in[2];
    const float* Wv   = (const float*)d_in[3];
    const float* Wo   = (const float*)d_in[4];
    const float* bo   = (const float*)d_in[5];
    const float* ln1w = (const float*)d_in[6];
    const float* ln1b = (const float*)d_in[7];
    const float* ln2w = (const float*)d_in[8];
    const float* ln2b = (const float*)d_in[9];
    const float* Wc   = (const float*)d_in[10];
    const float* bc   = (const float*)d_in[11];

    float* out    = (float*)d_out;
    float* logits = out;           // [8,10]
    float* xout   = out + B_ * 10; // [8,2048,768]

    __half *srch, *Qh, *Kh, *Vh, *Sch, *ctxh, *Wqh, *Wkh, *Wvh, *Woh;
    float *ao, *pooled;
    cudaGetSymbolAddress((void**)&srch,   g_srch);
    cudaGetSymbolAddress((void**)&Qh,     g_Qh);
    cudaGetSymbolAddress((void**)&Kh,     g_Kh);
    cudaGetSymbolAddress((void**)&Vh,     g_Vh);
    cudaGetSymbolAddress((void**)&Sch,    g_Sch);
    cudaGetSymbolAddress((void**)&ctxh,   g_ctxh);
    cudaGetSymbolAddress((void**)&ao,     g_ao);
    cudaGetSymbolAddress((void**)&pooled, g_pooled);
    cudaGetSymbolAddress((void**)&Wqh,    g_Wqh);
    cudaGetSymbolAddress((void**)&Wkh,    g_Wkh);
    cudaGetSymbolAddress((void**)&Wvh,    g_Wvh);
    cudaGetSymbolAddress((void**)&Woh,    g_Woh);

    // 0) fp32 -> fp16 (src + weights, native [K,N] layouts kept)
    f2h_kernel<<<(MTOT * D_ / 4 + 255) / 256, 256>>>(src, srch, MTOT * D_ / 4);
    {
        const int n4 = D_ * DK_ / 4;
        f2h_kernel<<<(n4 + 255) / 256, 256>>>(Wq, Wqh, n4);
        f2h_kernel<<<(n4 + 255) / 256, 256>>>(Wk, Wkh, n4);
        f2h_kernel<<<(n4 + 255) / 256, 256>>>(Wv, Wvh, n4);
        f2h_kernel<<<(n4 + 255) / 256, 256>>>(Wo, Woh, n4);
    }
    // 1) Q,K,V = src @ W*  (B = [K,N] native)
    {
        dim3 grid(DK_ / 128, MTOT / 128, 1);
        gemm_h<1, true><<<grid, 256>>>(srch, Wqh, Qh, MTOT, DK_, D_, DK_, 1.0f, 0, 0, 0);
        gemm_h<1, true><<<grid, 256>>>(srch, Wkh, Kh, MTOT, DK_, D_, DK_, 1.0f, 0, 0, 0);
        gemm_h<1, true><<<grid, 256>>>(srch, Wvh, Vh, MTOT, DK_, D_, DK_, 1.0f, 0, 0, 0);
    }
    // 2) scores = Q @ K^T * 1/sqrt(DK)  (B = K-matrix [t,d] = [N,K]), fp16 out
    {
        dim3 grid(S_ / 128, S_ / 128, B_);
        const float alpha = rsqrtf((float)DK_);
        gemm_h<0, true><<<grid, 256>>>(Qh, Kh, Sch, S_, S_, DK_, DK_, alpha,
                                       (size_t)S_ * DK_, (size_t)S_ * DK_,
                                       (size_t)S_ * S_);
    }
    // 3) softmax rows in place (fp16)
    softmax_kernel<<<B_ * S_, 256>>>(Sch);
    // 4) ctx = probs @ V  (B = V [t,d] = [K,N] native)
    {
        dim3 grid(DK_ / 128, S_ / 128, B_);
        gemm_h<1, true><<<grid, 256>>>(Sch, Vh, ctxh, S_, DK_, S_, DK_, 1.0f,
                                       (size_t)S_ * S_, (size_t)S_ * DK_,
                                       (size_t)S_ * DK_);
    }
    // 5) ao = ctx @ Wo  (B = [K,N] native), fp32 out; bo folded into resid
    {
        dim3 grid(D_ / 128, MTOT / 128, 1);
        gemm_h<1, false><<<grid, 256>>>(ctxh, Woh, ao, MTOT, D_, DK_, D_, 1.0f, 0, 0, 0);
    }
    // 6) x = LN2(LN1(src + ao + bo))
    resid_ln2_kernel<<<MTOT, 256>>>(src, ao, bo, ln1w, ln1b, ln2w, ln2b, xout);
    // 7) pooled mean over S
    {
        dim3 grid(D_ / 256, B_);
        pool_kernel<<<grid, 256>>>(xout, pooled);
    }
    // 8) logits
    logits_kernel<<<B_ * 10, 128>>>(pooled, Wc, bc, logits);
}

// round 7
// speedup vs baseline: 6.2190x; 1.0688x over previous
#include <cuda_runtime.h>
#include <cuda_fp16.h>
#include <cstdint>
#include <math.h>

#define B_ 8
#define S_ 2048
#define D_ 768
#define DK_ 768
#define MTOT (B_ * S_)   // 16384
#define EPS_ 1e-5f

// ---------------- scratch (device globals; no allocations allowed) ----------
__device__ __align__(16) __half g_srch[(size_t)MTOT * D_];
__device__ __align__(16) __half g_QKV[(size_t)3 * MTOT * DK_];   // Q|K|V packed
__device__ __align__(16) __half g_Wh3[(size_t)3 * D_ * DK_];     // Wq|Wk|Wv packed
__device__ __align__(16) __half g_Woh[DK_ * D_];
__device__ __align__(16) __half g_Sch[(size_t)B_ * S_ * S_];     // scores->probs fp16
__device__ __align__(16) __half g_ctxh[(size_t)MTOT * DK_];
__device__ float g_ao[(size_t)MTOT * D_];
__device__ float g_pooled[B_ * D_];

// ---------------- helpers ----------------------------------------------------
__device__ __forceinline__ void cp_async16(void* sp, const void* gp) {
    unsigned s = (unsigned)__cvta_generic_to_shared(sp);
    asm volatile("cp.async.cg.shared.global [%0], [%1], 16;\n" :: "r"(s), "l"(gp));
}
__device__ __forceinline__ void mma_f16(float* d, const uint32_t* a, const uint32_t* b) {
    asm volatile(
        "mma.sync.aligned.m16n8k16.row.col.f32.f16.f16.f32 "
        "{%0,%1,%2,%3}, {%4,%5,%6,%7}, {%8,%9}, {%0,%1,%2,%3};"
        : "+f"(d[0]), "+f"(d[1]), "+f"(d[2]), "+f"(d[3])
        : "r"(a[0]), "r"(a[1]), "r"(a[2]), "r"(a[3]), "r"(b[0]), "r"(b[1]));
}
__device__ __forceinline__ void ldsm_x4(uint32_t& r0, uint32_t& r1, uint32_t& r2,
                                        uint32_t& r3, uint32_t addr) {
    asm volatile("ldmatrix.sync.aligned.m8n8.x4.shared.b16 {%0,%1,%2,%3}, [%4];"
                 : "=r"(r0), "=r"(r1), "=r"(r2), "=r"(r3) : "r"(addr));
}
__device__ __forceinline__ void ldsm_x4_t(uint32_t& r0, uint32_t& r1, uint32_t& r2,
                                          uint32_t& r3, uint32_t addr) {
    asm volatile("ldmatrix.sync.aligned.m8n8.x4.trans.shared.b16 {%0,%1,%2,%3}, [%4];"
                 : "=r"(r0), "=r"(r1), "=r"(r2), "=r"(r3) : "r"(addr));
}

// ---------------- FP16 mma.sync GEMM -----------------------------------------
// C[M,N] = alpha * A[M,K] @ B, A half K-major.
// BMODE 0: B is [N,K] (K-major).  BMODE 1: B is [K,N] (ldmatrix.trans).
// 128x128 CTA tile, BK=32, 3-stage cp.async (1 sync/iter), 8 warps (4Mx2N).
#define RS_A 40                          // A / K-major B row stride (halves)
#define RS_BT 136                        // [K,N] B row stride (halves)
#define A_TILE_H (128 * RS_A)            // 5120 halves
#define B_TILE_H (128 * RS_A)            // covers both layouts (32*136=4352 < 5120)
#define STAGE_H (A_TILE_H + B_TILE_H)    // 10240 halves = 20480 B
#define NSTAGE 3
#define GEMM_SMEM (NSTAGE * STAGE_H * 2) // 61440 B

template <int BMODE, bool HALF_OUT>
__global__ void __launch_bounds__(256, 2) gemm_h(
    const __half* __restrict__ A, const __half* __restrict__ Bm,
    void* __restrict__ Cv, int M, int N, int K, int ldB, float alpha,
    size_t sA, size_t sB, size_t sC)
{
    extern __shared__ __half smem[];

    A  += blockIdx.z * sA;
    Bm += blockIdx.z * sB;

    const int tid = threadIdx.x;
    const int wid = tid >> 5;
    const int lane = tid & 31;
    const int gid = lane >> 2;     // 0..7
    const int tig = lane & 3;      // 0..3
    const int mat = lane >> 3;     // 0..3 (ldmatrix address group)
    const int rw = lane & 7;       // row within 8x8 mat
    const int wm = wid >> 1;       // 0..3 -> rows wm*32
    const int wn = wid & 1;        // 0..1 -> cols wn*64
    const int m0 = blockIdx.y * 128;
    const int n0 = blockIdx.x * 128;

    const uint32_t smem_base = (uint32_t)__cvta_generic_to_shared(smem);

    float acc[2][8][4];
    #pragma unroll
    for (int i = 0; i < 2; i++)
        #pragma unroll
        for (int j = 0; j < 8; j++)
            #pragma unroll
            for (int t = 0; t < 4; t++) acc[i][j][t] = 0.0f;

    auto load_tile = [&](int t, int st) {
        __half* sa = smem + st * STAGE_H;
        __half* sb = sa + A_TILE_H;
        const int k0 = t * 32;
        #pragma unroll
        for (int i = 0; i < 2; i++) {
            int id = i * 256 + tid;
            int row = id >> 2, c8 = (id & 3) * 8;
            cp_async16(sa + row * RS_A + c8, A + (size_t)(m0 + row) * K + k0 + c8);
        }
        if (BMODE == 0) {
            #pragma unroll
            for (int i = 0; i < 2; i++) {
                int id = i * 256 + tid;
                int row = id >> 2, c8 = (id & 3) * 8;
                cp_async16(sb + row * RS_A + c8, Bm + (size_t)(n0 + row) * ldB + k0 + c8);
            }
        } else {
            #pragma unroll
            for (int i = 0; i < 2; i++) {
                int id = i * 256 + tid;
                int row = id >> 4, c8 = (id & 15) * 8;
                cp_async16(sb + row * RS_BT + c8, Bm + (size_t)(k0 + row) * ldB + n0 + c8);
            }
        }
        asm volatile("cp.async.commit_group;\n" ::);
    };

    auto compute = [&](int st) {
        const uint32_t sa = smem_base + (uint32_t)(st * STAGE_H) * 2u;
        const uint32_t sb = sa + A_TILE_H * 2u;
        #pragma unroll
        for (int k16 = 0; k16 < 2; k16++) {
            const int kb = k16 * 16;
            uint32_t af[2][4];
            #pragma unroll
            for (int i = 0; i < 2; i++) {
                uint32_t addr = sa + 2u * ((wm * 32 + i * 16 + (mat & 1) * 8 + rw) * RS_A
                                           + kb + (mat >> 1) * 8);
                ldsm_x4(af[i][0], af[i][1], af[i][2], af[i][3], addr);
            }
            uint32_t bf[8][2];
            #pragma unroll
            for (int jp = 0; jp < 4; jp++) {
                const int n = wn * 64 + jp * 16;
                if (BMODE == 0) {
                    uint32_t addr = sb + 2u * ((n + (mat >> 1) * 8 + rw) * RS_A
                                               + kb + (mat & 1) * 8);
                    ldsm_x4(bf[2 * jp][0], bf[2 * jp][1], bf[2 * jp + 1][0],
                            bf[2 * jp + 1][1], addr);
                } else {
                    uint32_t addr = sb + 2u * ((kb + (mat & 1) * 8 + rw) * RS_BT
                                               + n + (mat >> 1) * 8);
                    ldsm_x4_t(bf[2 * jp][0], bf[2 * jp][1], bf[2 * jp + 1][0],
                              bf[2 * jp + 1][1], addr);
                }
            }
            #pragma unroll
            for (int i = 0; i < 2; i++)
                #pragma unroll
                for (int j = 0; j < 8; j++)
                    mma_f16(acc[i][j], af[i], bf[j]);
        }
    };

    const int nk = K / 32;
    load_tile(0, 0);
    if (nk > 1) load_tile(1, 1);

    int st = 0;                       // stage of tile s
    for (int s = 0; s < nk; s++) {
        if (s < nk - 1) asm volatile("cp.async.wait_group 1;\n" ::);
        else            asm volatile("cp.async.wait_group 0;\n" ::);
        __syncthreads();
        if (s + 2 < nk) {
            int st2 = st + 2; if (st2 >= NSTAGE) st2 -= NSTAGE;
            load_tile(s + 2, st2);
        }
        compute(st);
        if (++st == NSTAGE) st = 0;
    }

    // epilogue
    if (HALF_OUT) {
        __half* C = (__half*)Cv + blockIdx.z * sC;
        #pragma unroll
        for (int i = 0; i < 2; i++) {
            const int rbase = m0 + wm * 32 + i * 16 + gid;
            #pragma unroll
            for (int j = 0; j < 8; j++) {
                const int col = n0 + wn * 64 + j * 8 + tig * 2;
                *(__half2*)(C + (size_t)rbase * N + col) =
                    __floats2half2_rn(acc[i][j][0] * alpha, acc[i][j][1] * alpha);
                *(__half2*)(C + (size_t)(rbase + 8) * N + col) =
                    __floats2half2_rn(acc[i][j][2] * alpha, acc[i][j][3] * alpha);
            }
        }
    } else {
        float* C = (float*)Cv + blockIdx.z * sC;
        #pragma unroll
        for (int i = 0; i < 2; i++) {
            const int rbase = m0 + wm * 32 + i * 16 + gid;
            #pragma unroll
            for (int j = 0; j < 8; j++) {
                const int col = n0 + wn * 64 + j * 8 + tig * 2;
                *(float2*)(C + (size_t)rbase * N + col) =
                    make_float2(acc[i][j][0] * alpha, acc[i][j][1] * alpha);
                *(float2*)(C + (size_t)(rbase + 8) * N + col) =
                    make_float2(acc[i][j][2] * alpha, acc[i][j][3] * alpha);
            }
        }
    }
}

// ---------------- fp32 -> fp16 ------------------------------------------------
__global__ void __launch_bounds__(256) f2h_kernel(const float* __restrict__ in,
                                                  __half* __restrict__ out, int n4) {
    int i = blockIdx.x * 256 + threadIdx.x;
    if (i < n4) {
        float4 v = ((const float4*)in)[i];
        ((__half2*)out)[2 * i]     = __floats2half2_rn(v.x, v.y);
        ((__half2*)out)[2 * i + 1] = __floats2half2_rn(v.z, v.w);
    }
}

// 4 weight matrices in one launch (blockIdx.y selects)
__global__ void __launch_bounds__(256) f2h4_kernel(
    const float* __restrict__ w0, const float* __restrict__ w1,
    const float* __restrict__ w2, const float* __restrict__ w3,
    __half* __restrict__ o0, __half* __restrict__ o1,
    __half* __restrict__ o2, __half* __restrict__ o3, int n4)
{
    const float* in;
    __half* out;
    switch (blockIdx.y) {
        case 0: in = w0; out = o0; break;
        case 1: in = w1; out = o1; break;
        case 2: in = w2; out = o2; break;
        default: in = w3; out = o3; break;
    }
    int i = blockIdx.x * 256 + threadIdx.x;
    if (i < n4) {
        float4 v = ((const float4*)in)[i];
        ((__half2*)out)[2 * i]     = __floats2half2_rn(v.x, v.y);
        ((__half2*)out)[2 * i + 1] = __floats2half2_rn(v.z, v.w);
    }
}

// ---------------- reductions -------------------------------------------------
__device__ __forceinline__ float warp_sum(float v) {
    #pragma unroll
    for (int o = 16; o > 0; o >>= 1) v += __shfl_xor_sync(0xFFFFFFFFu, v, o);
    return v;
}
__device__ __forceinline__ float warp_max(float v) {
    #pragma unroll
    for (int o = 16; o > 0; o >>= 1) v = fmaxf(v, __shfl_xor_sync(0xFFFFFFFFu, v, o));
    return v;
}
__device__ __forceinline__ float block_sum(float v, float* sh) {
    __syncthreads();
    int lane = threadIdx.x & 31, w = threadIdx.x >> 5;
    v = warp_sum(v);
    if (lane == 0) sh[w] = v;
    __syncthreads();
    float r = (threadIdx.x < (blockDim.x >> 5)) ? sh[threadIdx.x] : 0.0f;
    if (w == 0) {
        r = warp_sum(r);
        if (lane == 0) sh[0] = r;
    }
    __syncthreads();
    return sh[0];
}
__device__ __forceinline__ float block_max(float v, float* sh) {
    __syncthreads();
    int lane = threadIdx.x & 31, w = threadIdx.x >> 5;
    v = warp_max(v);
    if (lane == 0) sh[w] = v;
    __syncthreads();
    float r = (threadIdx.x < (blockDim.x >> 5)) ? sh[threadIdx.x] : -INFINITY;
    if (w == 0) {
        r = warp_max(r);
        if (lane == 0) sh[0] = r;
    }
    __syncthreads();
    return sh[0];
}

// ---------------- row softmax fp16 in-place ----------------------------------
__global__ void __launch_bounds__(256) softmax_kernel(__half* __restrict__ Sc) {
    __shared__ float sh[32];
    const size_t row = blockIdx.x;
    __half2* p = (__half2*)(Sc + row * (size_t)S_);
    const int tid = threadIdx.x;

    float2 v[4];
    float mx = -INFINITY;
    #pragma unroll
    for (int i = 0; i < 4; i++) {
        v[i] = __half22float2(p[tid + i * 256]);
        mx = fmaxf(mx, fmaxf(v[i].x, v[i].y));
    }
    mx = block_max(mx, sh);

    float s = 0.0f;
    #pragma unroll
    for (int i = 0; i < 4; i++) {
        v[i].x = __expf(v[i].x - mx);
        v[i].y = __expf(v[i].y - mx);
        s += v[i].x + v[i].y;
    }
    s = block_sum(s, sh);
    const float inv = 1.0f / s;
    #pragma unroll
    for (int i = 0; i < 4; i++)
        p[tid + i * 256] = __floats2half2_rn(v[i].x * inv, v[i].y * inv);
}

// ---------------- residual(+bo) + LN + LN, fused -----------------------------
__global__ void __launch_bounds__(256) resid_ln2_kernel(
    const float* __restrict__ src, const float* __restrict__ ao,
    const float* __restrict__ bo,
    const float* __restrict__ w1, const float* __restrict__ b1,
    const float* __restrict__ w2, const float* __restrict__ b2,
    float* __restrict__ xout)
{
    __shared__ float sh[32];
    const size_t row = blockIdx.x;
    const int tid = threadIdx.x;
    const size_t base = row * (size_t)D_;

    float v[3];
    int d[3];
    #pragma unroll
    for (int i = 0; i < 3; i++) {
        d[i] = tid + i * 256;
        v[i] = src[base + d[i]] + ao[base + d[i]] + bo[d[i]];
    }

    float s = v[0] + v[1] + v[2];
    s = block_sum(s, sh);
    const float mu1 = s * (1.0f / (float)D_);
    float sq = 0.0f;
    #pragma unroll
    for (int i = 0; i < 3; i++) { float t = v[i] - mu1; sq += t * t; }
    sq = block_sum(sq, sh);
    const float r1 = rsqrtf(sq * (1.0f / (float)D_) + EPS_);
    #pragma unroll
    for (int i = 0; i < 3; i++)
        v[i] = (v[i] - mu1) * r1 * w1[d[i]] + b1[d[i]];

    s = v[0] + v[1] + v[2];
    s = block_sum(s, sh);
    const float mu2 = s * (1.0f / (float)D_);
    sq = 0.0f;
    #pragma unroll
    for (int i = 0; i < 3; i++) { float t = v[i] - mu2; sq += t * t; }
    sq = block_sum(sq, sh);
    const float r2 = rsqrtf(sq * (1.0f / (float)D_) + EPS_);
    #pragma unroll
    for (int i = 0; i < 3; i++)
        xout[base + d[i]] = (v[i] - mu2) * r2 * w2[d[i]] + b2[d[i]];
}

// ---------------- pooled mean over S ----------------------------------------
__global__ void __launch_bounds__(256) pool_kernel(const float* __restrict__ x,
                                                   float* __restrict__ pooled) {
    const int b = blockIdx.y;
    const int dd = blockIdx.x * 256 + threadIdx.x;
    const float* p = x + (size_t)b * S_ * D_ + dd;
    float s = 0.0f;
    for (int t = 0; t < S_; t++) s += p[(size_t)t * D_];
    pooled[b * D_ + dd] = s * (1.0f / (float)S_);
}

// ---------------- logits -----------------------------------------------------
__global__ void __launch_bounds__(128) logits_kernel(
    const float* __restrict__ pooled, const float* __restrict__ Wc,
    const float* __restrict__ bc, float* __restrict__ out)
{
    __shared__ float sh[32];
    const int idx = blockIdx.x;
    const int b = idx / 10, o = idx % 10;
    float s = 0.0f;
    for (int dd = threadIdx.x; dd < D_; dd += 128)
        s += pooled[b * D_ + dd] * Wc[dd * 10 + o];
    s = block_sum(s, sh);
    if (threadIdx.x == 0) out[b * 10 + o] = s + bc[o];
}

// ---------------- launch -----------------------------------------------------
extern "C" void kernel_launch(void* const* d_in, const int* in_sizes, int n_in,
                              void* d_out, int out_size) {
    const float* src  = (const float*)d_in[0];
    const float* Wq   = (const float*)d_in[1];
    const float* Wk   = (const float*)d_in[2];
    const float* Wv   = (const float*)d_in[3];
    const float* Wo   = (const float*)d_in[4];
    const float* bo   = (const float*)d_in[5];
    const float* ln1w = (const float*)d_in[6];
    const float* ln1b = (const float*)d_in[7];
    const float* ln2w = (const float*)d_in[8];
    const float* ln2b = (const float*)d_in[9];
    const float* Wc   = (const float*)d_in[10];
    const float* bc   = (const float*)d_in[11];

    float* out    = (float*)d_out;
    float* logits = out;           // [8,10]
    float* xout   = out + B_ * 10; // [8,2048,768]

    __half *srch, *QKV, *Wh3, *Woh, *Sch, *ctxh;
    float *ao, *pooled;
    cudaGetSymbolAddress((void**)&srch,   g_srch);
    cudaGetSymbolAddress((void**)&QKV,    g_QKV);
    cudaGetSymbolAddress((void**)&Wh3,    g_Wh3);
    cudaGetSymbolAddress((void**)&Woh,    g_Woh);
    cudaGetSymbolAddress((void**)&Sch,    g_Sch);
    cudaGetSymbolAddress((void**)&ctxh,   g_ctxh);
    cudaGetSymbolAddress((void**)&ao,     g_ao);
    cudaGetSymbolAddress((void**)&pooled, g_pooled);

    __half* Qh = QKV;
    __half* Kh = QKV + (size_t)MTOT * DK_;
    __half* Vh = QKV + (size_t)2 * MTOT * DK_;

    cudaFuncSetAttribute(gemm_h<1, true>,  cudaFuncAttributeMaxDynamicSharedMemorySize, GEMM_SMEM);
    cudaFuncSetAttribute(gemm_h<0, true>,  cudaFuncAttributeMaxDynamicSharedMemorySize, GEMM_SMEM);
    cudaFuncSetAttribute(gemm_h<1, false>, cudaFuncAttributeMaxDynamicSharedMemorySize, GEMM_SMEM);

    // 0) fp32 -> fp16: src + all 4 weight matrices (one launch for weights)
    f2h_kernel<<<(MTOT * D_ / 4 + 255) / 256, 256>>>(src, srch, MTOT * D_ / 4);
    {
        const int n4 = D_ * DK_ / 4;
        dim3 grid((n4 + 255) / 256, 4);
        f2h4_kernel<<<grid, 256>>>(Wq, Wk, Wv, Wo,
                                   Wh3, Wh3 + (size_t)D_ * DK_,
                                   Wh3 + (size_t)2 * D_ * DK_, Woh, n4);
    }
    // 1) Q,K,V = src @ W*  — single launch, z selects matrix
    {
        dim3 grid(DK_ / 128, MTOT / 128, 3);
        gemm_h<1, true><<<grid, 256, GEMM_SMEM>>>(
            srch, Wh3, QKV, MTOT, DK_, D_, DK_, 1.0f,
            0, (size_t)D_ * DK_, (size_t)MTOT * DK_);
    }
    // 2) scores = Q @ K^T * 1/sqrt(DK)  (B = K [t,d] = [N,K]), fp16 out
    {
        dim3 grid(S_ / 128, S_ / 128, B_);
        const float alpha = rsqrtf((float)DK_);
        gemm_h<0, true><<<grid, 256, GEMM_SMEM>>>(
            Qh, Kh, Sch, S_, S_, DK_, DK_, alpha,
            (size_t)S_ * DK_, (size_t)S_ * DK_, (size_t)S_ * S_);
    }
    // 3) softmax rows in place (fp16)
    softmax_kernel<<<B_ * S_, 256>>>(Sch);
    // 4) ctx = probs @ V  (B = V [t,d] = [K,N] native)
    {
        dim3 grid(DK_ / 128, S_ / 128, B_);
        gemm_h<1, true><<<grid, 256, GEMM_SMEM>>>(
            Sch, Vh, ctxh, S_, DK_, S_, DK_, 1.0f,
            (size_t)S_ * S_, (size_t)S_ * DK_, (size_t)S_ * DK_);
    }
    // 5) ao = ctx @ Wo  (B = [K,N] native), fp32 out; bo folded into resid
    {
        dim3 grid(D_ / 128, MTOT / 128, 1);
        gemm_h<1, false><<<grid, 256, GEMM_SMEM>>>(
            ctxh, Woh, ao, MTOT, D_, DK_, D_, 1.0f, 0, 0, 0);
    }
    // 6) x = LN2(LN1(src + ao + bo))
    resid_ln2_kernel<<<MTOT, 256>>>(src, ao, bo, ln1w, ln1b, ln2w, ln2b, xout);
    // 7) pooled mean over S
    {
        dim3 grid(D_ / 256, B_);
        pool_kernel<<<grid, 256>>>(xout, pooled);
    }
    // 8) logits
    logits_kernel<<<B_ * 10, 128>>>(pooled, Wc, bc, logits);
}